// round 2
// baseline (speedup 1.0000x reference)
#include <cuda_runtime.h>
#include <cuda_bf16.h>
#include <math.h>

// Problem constants (fixed by the dataset)
#define N_TOK 2048
#define D_MOD 2048
#define NHEAD 16
#define DHEAD 128
#define NQ    256          // rows n < 256 are the only rows with non-empty key sets
#define EPS   1e-5f

// ---------------- scratch (static __device__ arrays; cudaMalloc is forbidden) ----
__device__ float          g_xn  [N_TOK * D_MOD];   // LayerNorm(x)
__device__ float          g_kraw[N_TOK * D_MOD];   // xn @ Wk (pre head-LN)
__device__ float          g_v   [N_TOK * D_MOD];   // xn @ Wv (fp32, stays fp32)
__device__ float          g_qraw[NQ    * D_MOD];   // xn @ Wq (first 256 rows)
__device__ __nv_bfloat16  g_kbf [N_TOK * D_MOD];   // head-LN(k) cast bf16
__device__ __nv_bfloat16  g_qbf [NQ    * D_MOD];   // head-LN(q) cast bf16
__device__ float          g_o   [NQ    * D_MOD];   // attention output (first 256 rows)

// ---------------- row LayerNorm over D=2048 ----------------
__global__ void ln_rows(const float* __restrict__ x, float* __restrict__ xn) {
    int row = blockIdx.x;
    int t = threadIdx.x;                       // 256 threads
    const float4* xr = (const float4*)(x + (size_t)row * D_MOD);
    float4 a = xr[t];
    float4 b = xr[t + 256];
    float s  = a.x + a.y + a.z + a.w + b.x + b.y + b.z + b.w;
    float ss = a.x*a.x + a.y*a.y + a.z*a.z + a.w*a.w
             + b.x*b.x + b.y*b.y + b.z*b.z + b.w*b.w;
    // warp reduce
    #pragma unroll
    for (int o = 16; o > 0; o >>= 1) {
        s  += __shfl_xor_sync(0xffffffffu, s,  o);
        ss += __shfl_xor_sync(0xffffffffu, ss, o);
    }
    __shared__ float bs[8], bss[8];
    int w = t >> 5, l = t & 31;
    if (l == 0) { bs[w] = s; bss[w] = ss; }
    __syncthreads();
    float ts = 0.f, tss = 0.f;
    #pragma unroll
    for (int i = 0; i < 8; i++) { ts += bs[i]; tss += bss[i]; }
    float mean = ts * (1.0f / D_MOD);
    float var  = tss * (1.0f / D_MOD) - mean * mean;
    float inv  = rsqrtf(var + EPS);
    float4* xo = (float4*)(xn + (size_t)row * D_MOD);
    a.x = (a.x - mean) * inv; a.y = (a.y - mean) * inv;
    a.z = (a.z - mean) * inv; a.w = (a.w - mean) * inv;
    b.x = (b.x - mean) * inv; b.y = (b.y - mean) * inv;
    b.z = (b.z - mean) * inv; b.w = (b.w - mean) * inv;
    xo[t] = a;
    xo[t + 256] = b;
}

// ---------------- per-head LayerNorm (DH=128) + cast to bf16 ----------------
// One warp per (row, head) segment of 128 contiguous floats.
__global__ void head_ln_cast(const float* __restrict__ raw,
                             __nv_bfloat16* __restrict__ out, int nseg) {
    int seg  = blockIdx.x * 8 + (threadIdx.x >> 5);
    int lane = threadIdx.x & 31;
    if (seg >= nseg) return;
    const float4* p = (const float4*)(raw + (size_t)seg * DHEAD);
    float4 v = p[lane];
    float s  = v.x + v.y + v.z + v.w;
    float ss = v.x*v.x + v.y*v.y + v.z*v.z + v.w*v.w;
    #pragma unroll
    for (int o = 16; o > 0; o >>= 1) {
        s  += __shfl_xor_sync(0xffffffffu, s,  o);
        ss += __shfl_xor_sync(0xffffffffu, ss, o);
    }
    float mean = s * (1.0f / DHEAD);
    float var  = ss * (1.0f / DHEAD) - mean * mean;
    float inv  = rsqrtf(var + EPS);
    __nv_bfloat162 o0 = __floats2bfloat162_rn((v.x - mean) * inv, (v.y - mean) * inv);
    __nv_bfloat162 o1 = __floats2bfloat162_rn((v.z - mean) * inv, (v.w - mean) * inv);
    __nv_bfloat162* op = (__nv_bfloat162*)(out + (size_t)seg * DHEAD);
    op[lane * 2 + 0] = o0;
    op[lane * 2 + 1] = o1;
}

// ---------------- tiled fp32 GEMM: C[M x 2048] = A[M x 2048] @ B[2048 x 2048] (+R) --
// 128x128 block tile, K-tile 16, 256 threads, 8x8 per thread.
#define BM 128
#define BN 128
#define BK 16
#define SPITCH 132

__global__ __launch_bounds__(256)
void gemm_tiled(const float* __restrict__ A, const float* __restrict__ B,
                const float* __restrict__ R, float* __restrict__ C) {
    __shared__ float As[BK * SPITCH];
    __shared__ float Bs[BK * SPITCH];
    int tid = threadIdx.x;
    int tx = tid & 15, ty = tid >> 4;
    int rowBase = blockIdx.y * BM;
    int colBase = blockIdx.x * BN;

    float rc[8][8];
    #pragma unroll
    for (int i = 0; i < 8; i++)
        #pragma unroll
        for (int j = 0; j < 8; j++) rc[i][j] = 0.f;

    for (int k0 = 0; k0 < 2048; k0 += BK) {
        #pragma unroll
        for (int p = 0; p < 2; p++) {
            int f = tid + p * 256;
            // A tile: 128 rows x 16 k, store k-major As[k][m]
            int ar = f >> 2;
            int ac = (f & 3) * 4;
            float4 av = *(const float4*)(A + (size_t)(rowBase + ar) * 2048 + k0 + ac);
            As[(ac + 0) * SPITCH + ar] = av.x;
            As[(ac + 1) * SPITCH + ar] = av.y;
            As[(ac + 2) * SPITCH + ar] = av.z;
            As[(ac + 3) * SPITCH + ar] = av.w;
            // B tile: 16 k x 128 cols, natural layout Bs[k][n]
            int br = f >> 5;
            int bc = (f & 31) * 4;
            float4 bv = *(const float4*)(B + (size_t)(k0 + br) * 2048 + colBase + bc);
            *(float4*)(Bs + br * SPITCH + bc) = bv;
        }
        __syncthreads();
        #pragma unroll
        for (int kk = 0; kk < BK; kk++) {
            float4 a0 = *(const float4*)(As + kk * SPITCH + ty * 8);
            float4 a1 = *(const float4*)(As + kk * SPITCH + ty * 8 + 4);
            float4 b0 = *(const float4*)(Bs + kk * SPITCH + tx * 8);
            float4 b1 = *(const float4*)(Bs + kk * SPITCH + tx * 8 + 4);
            float av[8] = {a0.x, a0.y, a0.z, a0.w, a1.x, a1.y, a1.z, a1.w};
            float bv[8] = {b0.x, b0.y, b0.z, b0.w, b1.x, b1.y, b1.z, b1.w};
            #pragma unroll
            for (int i = 0; i < 8; i++)
                #pragma unroll
                for (int j = 0; j < 8; j++)
                    rc[i][j] += av[i] * bv[j];
        }
        __syncthreads();
    }

    #pragma unroll
    for (int i = 0; i < 8; i++) {
        int r = rowBase + ty * 8 + i;
        int c = colBase + tx * 8;
        float4 v0 = make_float4(rc[i][0], rc[i][1], rc[i][2], rc[i][3]);
        float4 v1 = make_float4(rc[i][4], rc[i][5], rc[i][6], rc[i][7]);
        if (R) {
            const float4* rp = (const float4*)(R + (size_t)r * 2048 + c);
            float4 r0 = rp[0], r1 = rp[1];
            v0.x += r0.x; v0.y += r0.y; v0.z += r0.z; v0.w += r0.w;
            v1.x += r1.x; v1.y += r1.y; v1.z += r1.z; v1.w += r1.w;
        }
        float4* cp = (float4*)(C + (size_t)r * 2048 + c);
        cp[0] = v0;
        cp[1] = v1;
    }
}

// ---------------- sparse attention ----------------
// Block = one (q row n < 256, head h). Keys: m = b + 16*j, j in [0,128), b = n>>4.
__global__ void attn_kernel(const __nv_bfloat16* __restrict__ qbf,
                            const __nv_bfloat16* __restrict__ kbf,
                            const float* __restrict__ v,
                            float* __restrict__ o) {
    int n = blockIdx.x;
    int h = blockIdx.y;
    int tid = threadIdx.x;  // 128 threads
    int b = n >> 4;

    __shared__ float qs[DHEAD];
    __shared__ __nv_bfloat16 ks[DHEAD * 130];  // pitch 130 -> conflict-free reads
    __shared__ float ps[DHEAD];
    __shared__ float sred[DHEAD];

    qs[tid] = __bfloat162float(qbf[(size_t)n * D_MOD + h * DHEAD + tid]);
    // cooperative k-tile load: iteration j loads key row (b + 16j), d = tid
    for (int j = 0; j < 128; j++)
        ks[j * 130 + tid] = kbf[(size_t)(b + 16 * j) * D_MOD + h * DHEAD + tid];
    __syncthreads();

    // score for key j = tid
    float s = 0.f;
    {
        int j = tid;
        #pragma unroll 16
        for (int d = 0; d < 128; d++)
            s += qs[d] * __bfloat162float(ks[j * 130 + d]);
    }
    s *= 0.08838834764831845f;  // 1/sqrt(128)

    // softmax over 128 keys
    sred[tid] = s;
    __syncthreads();
    #pragma unroll
    for (int off = 64; off > 0; off >>= 1) {
        if (tid < off) sred[tid] = fmaxf(sred[tid], sred[tid + off]);
        __syncthreads();
    }
    float mx = sred[0];
    __syncthreads();
    float p = __expf(s - mx);
    ps[tid] = p;
    sred[tid] = p;
    __syncthreads();
    #pragma unroll
    for (int off = 64; off > 0; off >>= 1) {
        if (tid < off) sred[tid] += sred[tid + off];
        __syncthreads();
    }
    float inv = 1.0f / fmaxf(sred[0], 1e-30f);

    // o[n,h,d] = (1/denom) * sum_j p_j * v[b+16j, h, d]  (d = tid, coalesced)
    float acc = 0.f;
    #pragma unroll 8
    for (int j = 0; j < 128; j++)
        acc += ps[j] * v[(size_t)(b + 16 * j) * D_MOD + h * DHEAD + tid];
    o[(size_t)n * D_MOD + h * DHEAD + tid] = acc * inv;
}

// ---------------- residual copy for rows >= 256 (attention output is exactly 0) ----
__global__ void copy_tail(const float* __restrict__ x, float* __restrict__ out) {
    size_t i = (size_t)blockIdx.x * blockDim.x + threadIdx.x;  // float4 index
    const size_t count = (size_t)(N_TOK - NQ) * D_MOD / 4;
    if (i < count) {
        const float4* xs = (const float4*)(x + (size_t)NQ * D_MOD);
        float4* od = (float4*)(out + (size_t)NQ * D_MOD);
        od[i] = xs[i];
    }
}

extern "C" void kernel_launch(void* const* d_in, const int* in_sizes, int n_in,
                              void* d_out, int out_size) {
    const float* x  = (const float*)d_in[0];
    const float* Wq = (const float*)d_in[1];
    const float* Wk = (const float*)d_in[2];
    const float* Wv = (const float*)d_in[3];
    const float* Wo = (const float*)d_in[4];
    float* out = (float*)d_out;

    float *xn, *kraw, *v, *qraw, *o;
    __nv_bfloat16 *kbf, *qbf;
    cudaGetSymbolAddress((void**)&xn,   g_xn);
    cudaGetSymbolAddress((void**)&kraw, g_kraw);
    cudaGetSymbolAddress((void**)&v,    g_v);
    cudaGetSymbolAddress((void**)&qraw, g_qraw);
    cudaGetSymbolAddress((void**)&o,    g_o);
    cudaGetSymbolAddress((void**)&kbf,  g_kbf);
    cudaGetSymbolAddress((void**)&qbf,  g_qbf);

    // 1) xn = LayerNorm(x)
    ln_rows<<<N_TOK, 256>>>(x, xn);
    // 2) K projection (all 2048 rows) -> per-head LN -> bf16
    gemm_tiled<<<dim3(16, 16), 256>>>(xn, Wk, nullptr, kraw);
    head_ln_cast<<<(N_TOK * NHEAD) / 8, 256>>>(kraw, kbf, N_TOK * NHEAD);
    // 3) V projection (all 2048 rows, fp32)
    gemm_tiled<<<dim3(16, 16), 256>>>(xn, Wv, nullptr, v);
    // 4) Q projection (only rows 0..255 can attend) -> per-head LN -> bf16
    gemm_tiled<<<dim3(16, 2), 256>>>(xn, Wq, nullptr, qraw);
    head_ln_cast<<<(NQ * NHEAD) / 8, 256>>>(qraw, qbf, NQ * NHEAD);
    // 5) sparse attention: 256 rows x 16 heads, 128 keys each
    attn_kernel<<<dim3(NQ, NHEAD), 128>>>(qbf, kbf, v, o);
    // 6) out[0:256] = o @ Wo + x ; out[256:] = x
    gemm_tiled<<<dim3(16, 2), 256>>>(o, Wo, x, out);
    copy_tail<<<(int)(((size_t)(N_TOK - NQ) * D_MOD / 4 + 255) / 256), 256>>>(x, out);
}

// round 4
// speedup vs baseline: 2.9955x; 2.9955x over previous
#include <cuda_runtime.h>
#include <cuda_bf16.h>
#include <math.h>
#include <stdint.h>

// Problem constants
#define N_TOK 2048
#define D_MOD 2048
#define NHEAD 16
#define DHEAD 128
#define NQ    256
#define EPS   1e-5f

// ---------------- device scratch ----------------
__device__ __nv_bfloat16 g_xnhi[N_TOK * D_MOD];
__device__ __nv_bfloat16 g_xnlo[N_TOK * D_MOD];
__device__ __nv_bfloat16 g_wkT_hi[D_MOD * D_MOD];
__device__ __nv_bfloat16 g_wkT_lo[D_MOD * D_MOD];
__device__ __nv_bfloat16 g_wvT_hi[D_MOD * D_MOD];
__device__ __nv_bfloat16 g_wvT_lo[D_MOD * D_MOD];
__device__ __nv_bfloat16 g_wqT_hi[D_MOD * D_MOD];
__device__ __nv_bfloat16 g_wqT_lo[D_MOD * D_MOD];
__device__ __nv_bfloat16 g_woT_hi[D_MOD * D_MOD];
__device__ __nv_bfloat16 g_woT_lo[D_MOD * D_MOD];
__device__ float          g_kraw[N_TOK * D_MOD];
__device__ float          g_v   [N_TOK * D_MOD];
__device__ float          g_qraw[NQ * D_MOD];
__device__ __nv_bfloat16  g_kbf [N_TOK * D_MOD];
__device__ __nv_bfloat16  g_qbf [NQ * D_MOD];
__device__ float          g_o   [NQ * D_MOD];
__device__ __nv_bfloat16  g_ohi [NQ * D_MOD];
__device__ __nv_bfloat16  g_olo [NQ * D_MOD];

// ---------------- helpers ----------------
__device__ __forceinline__ uint32_t smem_u32(const void* p) {
    uint32_t a;
    asm("{ .reg .u64 t; cvta.to.shared.u64 t, %1; cvt.u32.u64 %0, t; }" : "=r"(a) : "l"(p));
    return a;
}
__device__ __forceinline__ void cpa16(uint32_t saddr, const void* gaddr) {
    asm volatile("cp.async.cg.shared.global [%0], [%1], 16;" :: "r"(saddr), "l"(gaddr));
}
__device__ __forceinline__ void ldsm4(uint32_t addr, uint32_t* r) {
    asm volatile("ldmatrix.sync.aligned.m8n8.x4.shared.b16 {%0,%1,%2,%3}, [%4];"
                 : "=r"(r[0]), "=r"(r[1]), "=r"(r[2]), "=r"(r[3]) : "r"(addr));
}
__device__ __forceinline__ void mma16816(float* c, const uint32_t* a, const uint32_t* b) {
    asm volatile("mma.sync.aligned.m16n8k16.row.col.f32.bf16.bf16.f32 "
        "{%0,%1,%2,%3}, {%4,%5,%6,%7}, {%8,%9}, {%0,%1,%2,%3};"
        : "+f"(c[0]), "+f"(c[1]), "+f"(c[2]), "+f"(c[3])
        : "r"(a[0]), "r"(a[1]), "r"(a[2]), "r"(a[3]), "r"(b[0]), "r"(b[1]));
}
__device__ __forceinline__ void split1(float v, __nv_bfloat16& h, __nv_bfloat16& l) {
    h = __float2bfloat16(v);
    l = __float2bfloat16(v - __bfloat162float(h));
}
__device__ __forceinline__ uint32_t swz(uint32_t off) {
    return off ^ ((off >> 3) & 0x70);
}

// ---------------- LayerNorm rows + split to bf16 hi/lo ----------------
__global__ void ln_split(const float* __restrict__ x,
                         __nv_bfloat16* __restrict__ hi, __nv_bfloat16* __restrict__ lo) {
    int row = blockIdx.x;
    int t = threadIdx.x;  // 256
    const float4* xr = (const float4*)(x + (size_t)row * D_MOD);
    float4 a = xr[t];
    float4 b = xr[t + 256];
    float s  = a.x + a.y + a.z + a.w + b.x + b.y + b.z + b.w;
    float ss = a.x*a.x + a.y*a.y + a.z*a.z + a.w*a.w
             + b.x*b.x + b.y*b.y + b.z*b.z + b.w*b.w;
    #pragma unroll
    for (int o = 16; o > 0; o >>= 1) {
        s  += __shfl_xor_sync(0xffffffffu, s,  o);
        ss += __shfl_xor_sync(0xffffffffu, ss, o);
    }
    __shared__ float bs[8], bss[8];
    int w = t >> 5, l = t & 31;
    if (l == 0) { bs[w] = s; bss[w] = ss; }
    __syncthreads();
    float ts = 0.f, tss = 0.f;
    #pragma unroll
    for (int i = 0; i < 8; i++) { ts += bs[i]; tss += bss[i]; }
    float mean = ts * (1.0f / D_MOD);
    float var  = tss * (1.0f / D_MOD) - mean * mean;
    float inv  = rsqrtf(var + EPS);

    float va[8] = {a.x, a.y, a.z, a.w, b.x, b.y, b.z, b.w};
    __nv_bfloat16 h8[8], l8[8];
    #pragma unroll
    for (int i = 0; i < 8; i++) split1((va[i] - mean) * inv, h8[i], l8[i]);
    __nv_bfloat162* hp = (__nv_bfloat162*)(hi + (size_t)row * D_MOD);
    __nv_bfloat162* lp = (__nv_bfloat162*)(lo + (size_t)row * D_MOD);
    hp[t*2 + 0]   = __nv_bfloat162(h8[0], h8[1]);
    hp[t*2 + 1]   = __nv_bfloat162(h8[2], h8[3]);
    hp[512 + t*2] = __nv_bfloat162(h8[4], h8[5]);
    hp[513 + t*2] = __nv_bfloat162(h8[6], h8[7]);
    lp[t*2 + 0]   = __nv_bfloat162(l8[0], l8[1]);
    lp[t*2 + 1]   = __nv_bfloat162(l8[2], l8[3]);
    lp[512 + t*2] = __nv_bfloat162(l8[4], l8[5]);
    lp[513 + t*2] = __nv_bfloat162(l8[6], l8[7]);
}

// ---------------- transpose W [K,N] -> Wt [N,K] + split hi/lo ----------------
__global__ void transpose_split(const float* __restrict__ W,
                                __nv_bfloat16* __restrict__ Thi,
                                __nv_bfloat16* __restrict__ Tlo) {
    __shared__ float tile[32][33];
    int x = blockIdx.x * 32 + threadIdx.x;  // n
    int y = blockIdx.y * 32 + threadIdx.y;  // k
    #pragma unroll
    for (int i = 0; i < 4; i++)
        tile[threadIdx.y + i*8][threadIdx.x] = W[(size_t)(y + i*8) * D_MOD + x];
    __syncthreads();
    int nx = blockIdx.y * 32 + threadIdx.x;  // k
    int ny = blockIdx.x * 32 + threadIdx.y;  // n
    #pragma unroll
    for (int i = 0; i < 4; i++) {
        float v = tile[threadIdx.x][threadIdx.y + i*8];
        __nv_bfloat16 h, l;
        split1(v, h, l);
        Thi[(size_t)(ny + i*8) * D_MOD + nx] = h;
        Tlo[(size_t)(ny + i*8) * D_MOD + nx] = l;
    }
}

// ---------------- split fp32 -> bf16 hi/lo elementwise ----------------
__global__ void split_arr(const float* __restrict__ src,
                          __nv_bfloat16* __restrict__ hi, __nv_bfloat16* __restrict__ lo,
                          int n) {
    int i = blockIdx.x * 256 + threadIdx.x;
    if (i < n) {
        __nv_bfloat16 h, l;
        split1(src[i], h, l);
        hi[i] = h;
        lo[i] = l;
    }
}

// ---------------- HMMA bf16x3 GEMM: C[M,2048] = A[M,2048] @ Bt^T (+R) ----------
// A hi/lo row-major [M,2048] bf16; Bt hi/lo [2048,2048] bf16 K-major (row n, contig k).
// 128x128 CTA tile, 8 warps (2x4), warp tile 64x32, BK=64, double-buffered cp.async.
#define BK 64
#define NSTAGE 32
#define STG_BYTES 65536   // 4 arrays x 16KB per stage
#define GEMM_SMEM (2 * STG_BYTES)

__global__ __launch_bounds__(256, 1)
void gemm_mma(const __nv_bfloat16* __restrict__ Ahi, const __nv_bfloat16* __restrict__ Alo,
              const __nv_bfloat16* __restrict__ Bhi, const __nv_bfloat16* __restrict__ Blo,
              float* __restrict__ C, const float* __restrict__ R) {
    extern __shared__ __align__(1024) char smem[];
    uint32_t sb = smem_u32(smem);
    int tid = threadIdx.x, wid = tid >> 5, lane = tid & 31;
    int wr = wid >> 2, wc = wid & 3;
    int rowBase = blockIdx.y * 128, colBase = blockIdx.x * 128;

    // per-thread load geometry (stage-invariant)
    int ch0 = tid;                 // chunk ids tid + p*256, p=0..3
    float acc[4][4][4];
    #pragma unroll
    for (int mi = 0; mi < 4; mi++)
        #pragma unroll
        for (int ni = 0; ni < 4; ni++)
            #pragma unroll
            for (int r = 0; r < 4; r++) acc[mi][ni][r] = 0.f;

    // ---- loader ----
    auto load_stage = [&](int s, int buf) {
        uint32_t so = sb + (uint32_t)buf * STG_BYTES;
        size_t kof = (size_t)s * BK;
        #pragma unroll
        for (int p = 0; p < 4; p++) {
            int chunk = ch0 + p * 256;
            int row = chunk >> 3, c = chunk & 7;
            uint32_t sw = swz((uint32_t)(row * 128 + c * 16));
            size_t ga = (size_t)(rowBase + row) * 2048 + kof + c * 8;
            size_t gb = (size_t)(colBase + row) * 2048 + kof + c * 8;
            cpa16(so + sw,         Ahi + ga);
            cpa16(so + 16384 + sw, Alo + ga);
            cpa16(so + 32768 + sw, Bhi + gb);
            cpa16(so + 49152 + sw, Blo + gb);
        }
        asm volatile("cp.async.commit_group;" ::: "memory");
    };

    load_stage(0, 0);
    load_stage(1, 1);

    for (int s = 0; s < NSTAGE; s++) {
        if (s + 2 < NSTAGE) asm volatile("cp.async.wait_group 1;" ::: "memory");
        else                asm volatile("cp.async.wait_group 0;" ::: "memory");
        __syncthreads();

        uint32_t so = sb + (uint32_t)(s & 1) * STG_BYTES;
        #pragma unroll
        for (int ks = 0; ks < 4; ks++) {
            uint32_t ah[4][4], al[4][4], bh[2][4], bl[2][4];
            #pragma unroll
            for (int mi = 0; mi < 4; mi++) {
                int row = wr * 64 + mi * 16 + (lane & 15);
                int ch  = ks * 2 + (lane >> 4);
                uint32_t sw = swz((uint32_t)(row * 128 + ch * 16));
                ldsm4(so + sw,         ah[mi]);
                ldsm4(so + 16384 + sw, al[mi]);
            }
            #pragma unroll
            for (int p = 0; p < 2; p++) {
                int row = wc * 32 + p * 16 + ((lane >> 4) << 3) + (lane & 7);
                int ch  = ks * 2 + ((lane >> 3) & 1);
                uint32_t sw = swz((uint32_t)(row * 128 + ch * 16));
                ldsm4(so + 32768 + sw, bh[p]);
                ldsm4(so + 49152 + sw, bl[p]);
            }
            #pragma unroll
            for (int mi = 0; mi < 4; mi++)
                #pragma unroll
                for (int ni = 0; ni < 4; ni++) {
                    const uint32_t* fh = &bh[ni >> 1][(ni & 1) * 2];
                    const uint32_t* fl = &bl[ni >> 1][(ni & 1) * 2];
                    mma16816(acc[mi][ni], ah[mi], fh);
                    mma16816(acc[mi][ni], ah[mi], fl);
                    mma16816(acc[mi][ni], al[mi], fh);
                }
        }
        __syncthreads();
        if (s + 2 < NSTAGE) load_stage(s + 2, s & 1);
    }

    // ---- epilogue ----
    #pragma unroll
    for (int mi = 0; mi < 4; mi++)
        #pragma unroll
        for (int ni = 0; ni < 4; ni++) {
            int m0  = rowBase + wr * 64 + mi * 16 + (lane >> 2);
            int col = colBase + wc * 32 + ni * 8 + (lane & 3) * 2;
            size_t i0 = (size_t)m0 * 2048 + col;
            size_t i1 = i0 + (size_t)8 * 2048;
            float2 v0 = make_float2(acc[mi][ni][0], acc[mi][ni][1]);
            float2 v1 = make_float2(acc[mi][ni][2], acc[mi][ni][3]);
            if (R) {
                float2 r0 = *(const float2*)(R + i0);
                float2 r1 = *(const float2*)(R + i1);
                v0.x += r0.x; v0.y += r0.y;
                v1.x += r1.x; v1.y += r1.y;
            }
            *(float2*)(C + i0) = v0;
            *(float2*)(C + i1) = v1;
        }
}

// ---------------- per-head LayerNorm (DH=128) + cast to bf16 ----------------
__global__ void head_ln_cast(const float* __restrict__ raw,
                             __nv_bfloat16* __restrict__ out, int nseg) {
    int seg  = blockIdx.x * 8 + (threadIdx.x >> 5);
    int lane = threadIdx.x & 31;
    if (seg >= nseg) return;
    const float4* p = (const float4*)(raw + (size_t)seg * DHEAD);
    float4 v = p[lane];
    float s  = v.x + v.y + v.z + v.w;
    float ss = v.x*v.x + v.y*v.y + v.z*v.z + v.w*v.w;
    #pragma unroll
    for (int o = 16; o > 0; o >>= 1) {
        s  += __shfl_xor_sync(0xffffffffu, s,  o);
        ss += __shfl_xor_sync(0xffffffffu, ss, o);
    }
    float mean = s * (1.0f / DHEAD);
    float var  = ss * (1.0f / DHEAD) - mean * mean;
    float inv  = rsqrtf(var + EPS);
    __nv_bfloat162 o0 = __floats2bfloat162_rn((v.x - mean) * inv, (v.y - mean) * inv);
    __nv_bfloat162 o1 = __floats2bfloat162_rn((v.z - mean) * inv, (v.w - mean) * inv);
    __nv_bfloat162* op = (__nv_bfloat162*)(out + (size_t)seg * DHEAD);
    op[lane * 2 + 0] = o0;
    op[lane * 2 + 1] = o1;
}

// ---------------- sparse attention: block = (b, h), 16 q rows share keys ------
#define KPITCH 132
#define ATT_SMEM (16*128*4 + 16*128*4 + 128*KPITCH*2)

__global__ __launch_bounds__(128)
void attn2(const __nv_bfloat16* __restrict__ qbf, const __nv_bfloat16* __restrict__ kbf,
           const float* __restrict__ v, float* __restrict__ o) {
    extern __shared__ __align__(16) char asmem[];
    float* qs = (float*)asmem;                            // [16][128]
    float* ps = (float*)(asmem + 8192);                   // [16][128]
    __nv_bfloat16* ks = (__nv_bfloat16*)(asmem + 16384);  // [128][KPITCH]
    __shared__ float redm[64], reds[64];
    int b = blockIdx.x, h = blockIdx.y;
    int tid = threadIdx.x, w = tid >> 5, lane = tid & 31;

    for (int idx = tid; idx < 16 * 128; idx += 128) {
        int r = idx >> 7, d = idx & 127;
        qs[idx] = __bfloat162float(qbf[(size_t)(16*b + r) * D_MOD + h * DHEAD + d]);
    }
    for (int j = 0; j < 128; j++)
        ks[j * KPITCH + tid] = kbf[(size_t)(b + 16*j) * D_MOD + h * DHEAD + tid];
    __syncthreads();

    float s[16];
    #pragma unroll
    for (int r = 0; r < 16; r++) s[r] = 0.f;
    int j = tid;
    for (int d4 = 0; d4 < 32; d4++) {
        __nv_bfloat162 kk0 = *(const __nv_bfloat162*)(ks + j * KPITCH + d4 * 4);
        __nv_bfloat162 kk1 = *(const __nv_bfloat162*)(ks + j * KPITCH + d4 * 4 + 2);
        float2 k01 = __bfloat1622float2(kk0);
        float2 k23 = __bfloat1622float2(kk1);
        #pragma unroll
        for (int r = 0; r < 16; r++) {
            float4 qv = *(const float4*)(qs + r * 128 + d4 * 4);
            s[r] += qv.x * k01.x + qv.y * k01.y + qv.z * k23.x + qv.w * k23.y;
        }
    }
    const float SC = 0.08838834764831845f;
    #pragma unroll
    for (int r = 0; r < 16; r++) s[r] *= SC;

    #pragma unroll
    for (int r = 0; r < 16; r++) {
        float m = s[r];
        #pragma unroll
        for (int off = 16; off > 0; off >>= 1) m = fmaxf(m, __shfl_xor_sync(0xffffffffu, m, off));
        if (lane == 0) redm[r * 4 + w] = m;
    }
    __syncthreads();
    #pragma unroll
    for (int r = 0; r < 16; r++) {
        float mx = fmaxf(fmaxf(redm[r*4], redm[r*4+1]), fmaxf(redm[r*4+2], redm[r*4+3]));
        float p = __expf(s[r] - mx);
        ps[r * 128 + j] = p;
        float t = p;
        #pragma unroll
        for (int off = 16; off > 0; off >>= 1) t += __shfl_xor_sync(0xffffffffu, t, off);
        if (lane == 0) reds[r * 4 + w] = t;
    }
    __syncthreads();
    float inv[16];
    #pragma unroll
    for (int r = 0; r < 16; r++)
        inv[r] = 1.0f / fmaxf(reds[r*4] + reds[r*4+1] + reds[r*4+2] + reds[r*4+3], 1e-30f);

    float acc[16];
    #pragma unroll
    for (int r = 0; r < 16; r++) acc[r] = 0.f;
    int d = tid;
    const float* vp = v + h * DHEAD + d;
    for (int jj = 0; jj < 128; jj++) {
        float vv = vp[(size_t)(b + 16*jj) * D_MOD];
        #pragma unroll
        for (int r = 0; r < 16; r++) acc[r] += ps[r * 128 + jj] * vv;
    }
    #pragma unroll
    for (int r = 0; r < 16; r++)
        o[(size_t)(16*b + r) * D_MOD + h * DHEAD + d] = acc[r] * inv[r];
}

// ---------------- residual copy for rows >= 256 ----------------
__global__ void copy_tail(const float* __restrict__ x, float* __restrict__ out) {
    size_t i = (size_t)blockIdx.x * blockDim.x + threadIdx.x;
    const size_t count = (size_t)(N_TOK - NQ) * D_MOD / 4;
    if (i < count) {
        const float4* xs = (const float4*)(x + (size_t)NQ * D_MOD);
        float4* od = (float4*)(out + (size_t)NQ * D_MOD);
        od[i] = xs[i];
    }
}

extern "C" void kernel_launch(void* const* d_in, const int* in_sizes, int n_in,
                              void* d_out, int out_size) {
    const float* x  = (const float*)d_in[0];
    const float* Wq = (const float*)d_in[1];
    const float* Wk = (const float*)d_in[2];
    const float* Wv = (const float*)d_in[3];
    const float* Wo = (const float*)d_in[4];
    float* out = (float*)d_out;

    __nv_bfloat16 *xnhi, *xnlo, *wkh, *wkl, *wvh, *wvl, *wqh, *wql, *woh, *wol;
    __nv_bfloat16 *kbf, *qbf, *ohi, *olo;
    float *kraw, *v, *qraw, *o;
    cudaGetSymbolAddress((void**)&xnhi, g_xnhi);
    cudaGetSymbolAddress((void**)&xnlo, g_xnlo);
    cudaGetSymbolAddress((void**)&wkh,  g_wkT_hi);
    cudaGetSymbolAddress((void**)&wkl,  g_wkT_lo);
    cudaGetSymbolAddress((void**)&wvh,  g_wvT_hi);
    cudaGetSymbolAddress((void**)&wvl,  g_wvT_lo);
    cudaGetSymbolAddress((void**)&wqh,  g_wqT_hi);
    cudaGetSymbolAddress((void**)&wql,  g_wqT_lo);
    cudaGetSymbolAddress((void**)&woh,  g_woT_hi);
    cudaGetSymbolAddress((void**)&wol,  g_woT_lo);
    cudaGetSymbolAddress((void**)&kraw, g_kraw);
    cudaGetSymbolAddress((void**)&v,    g_v);
    cudaGetSymbolAddress((void**)&qraw, g_qraw);
    cudaGetSymbolAddress((void**)&o,    g_o);
    cudaGetSymbolAddress((void**)&kbf,  g_kbf);
    cudaGetSymbolAddress((void**)&qbf,  g_qbf);
    cudaGetSymbolAddress((void**)&ohi,  g_ohi);
    cudaGetSymbolAddress((void**)&olo,  g_olo);

    cudaFuncSetAttribute(gemm_mma, cudaFuncAttributeMaxDynamicSharedMemorySize, GEMM_SMEM);
    cudaFuncSetAttribute(attn2,    cudaFuncAttributeMaxDynamicSharedMemorySize, ATT_SMEM);

    // 1) LN + split
    ln_split<<<N_TOK, 256>>>(x, xnhi, xnlo);
    // 2) transpose + split all weights
    transpose_split<<<dim3(64, 64), dim3(32, 8)>>>(Wk, wkh, wkl);
    transpose_split<<<dim3(64, 64), dim3(32, 8)>>>(Wv, wvh, wvl);
    transpose_split<<<dim3(64, 64), dim3(32, 8)>>>(Wq, wqh, wql);
    transpose_split<<<dim3(64, 64), dim3(32, 8)>>>(Wo, woh, wol);
    // 3) K projection -> head LN -> bf16
    gemm_mma<<<dim3(16, 16), 256, GEMM_SMEM>>>(xnhi, xnlo, wkh, wkl, kraw, nullptr);
    head_ln_cast<<<(N_TOK * NHEAD) / 8, 256>>>(kraw, kbf, N_TOK * NHEAD);
    // 4) V projection (fp32)
    gemm_mma<<<dim3(16, 16), 256, GEMM_SMEM>>>(xnhi, xnlo, wvh, wvl, v, nullptr);
    // 5) Q projection (rows 0..255) -> head LN -> bf16
    gemm_mma<<<dim3(16, 2), 256, GEMM_SMEM>>>(xnhi, xnlo, wqh, wql, qraw, nullptr);
    head_ln_cast<<<(NQ * NHEAD) / 8, 256>>>(qraw, qbf, NQ * NHEAD);
    // 6) sparse attention (16 q rows per block share the key set)
    attn2<<<dim3(16, 16), 128, ATT_SMEM>>>(qbf, kbf, v, o);
    // 7) split o, then out[0:256] = o @ Wo + x
    split_arr<<<(NQ * D_MOD + 255) / 256, 256>>>(o, ohi, olo, NQ * D_MOD);
    gemm_mma<<<dim3(16, 2), 256, GEMM_SMEM>>>(ohi, olo, woh, wol, out, x);
    // 8) out[256:] = x
    copy_tail<<<(int)(((size_t)(N_TOK - NQ) * D_MOD / 4 + 255) / 256), 256>>>(x, out);
}

// round 5
// speedup vs baseline: 6.8059x; 2.2720x over previous
#include <cuda_runtime.h>
#include <cuda_fp16.h>
#include <cuda_bf16.h>
#include <math.h>
#include <stdint.h>

// Problem constants
#define N_TOK 2048
#define D_MOD 2048
#define NHEAD 16
#define DHEAD 128
#define NQ    256
#define EPS   1e-5f

// ---------------- device scratch ----------------
__device__ __half         g_xnh [N_TOK * D_MOD];   // LN(x) fp16
__device__ __half         g_wqT [D_MOD * D_MOD];   // W^T fp16 (K-major per out-col)
__device__ __half         g_wkT [D_MOD * D_MOD];
__device__ __half         g_wvT [D_MOD * D_MOD];
__device__ __half         g_woT [D_MOD * D_MOD];
__device__ float          g_kraw[N_TOK * D_MOD];
__device__ float          g_v   [N_TOK * D_MOD];
__device__ float          g_qraw[NQ * D_MOD];
__device__ __nv_bfloat16  g_kbf [N_TOK * D_MOD];
__device__ __nv_bfloat16  g_qbf [NQ * D_MOD];
__device__ float          g_o   [NQ * D_MOD];
__device__ __half         g_oh  [NQ * D_MOD];

// ---------------- helpers ----------------
__device__ __forceinline__ uint32_t smem_u32(const void* p) {
    uint32_t a;
    asm("{ .reg .u64 t; cvta.to.shared.u64 t, %1; cvt.u32.u64 %0, t; }" : "=r"(a) : "l"(p));
    return a;
}
__device__ __forceinline__ void cpa16(uint32_t saddr, const void* gaddr) {
    asm volatile("cp.async.cg.shared.global [%0], [%1], 16;" :: "r"(saddr), "l"(gaddr));
}
__device__ __forceinline__ void ldsm4(uint32_t addr, uint32_t* r) {
    asm volatile("ldmatrix.sync.aligned.m8n8.x4.shared.b16 {%0,%1,%2,%3}, [%4];"
                 : "=r"(r[0]), "=r"(r[1]), "=r"(r[2]), "=r"(r[3]) : "r"(addr));
}
__device__ __forceinline__ void mma16816(float* c, const uint32_t* a, const uint32_t* b) {
    asm volatile("mma.sync.aligned.m16n8k16.row.col.f32.f16.f16.f32 "
        "{%0,%1,%2,%3}, {%4,%5,%6,%7}, {%8,%9}, {%0,%1,%2,%3};"
        : "+f"(c[0]), "+f"(c[1]), "+f"(c[2]), "+f"(c[3])
        : "r"(a[0]), "r"(a[1]), "r"(a[2]), "r"(a[3]), "r"(b[0]), "r"(b[1]));
}
__device__ __forceinline__ uint32_t swz(uint32_t off) {
    return off ^ ((off >> 3) & 0x70);
}

// ---------------- LayerNorm rows -> fp16 ----------------
__global__ void ln_f16(const float* __restrict__ x, __half* __restrict__ xh) {
    int row = blockIdx.x;
    int t = threadIdx.x;  // 256
    const float4* xr = (const float4*)(x + (size_t)row * D_MOD);
    float4 a = xr[t];
    float4 b = xr[t + 256];
    float s  = a.x + a.y + a.z + a.w + b.x + b.y + b.z + b.w;
    float ss = a.x*a.x + a.y*a.y + a.z*a.z + a.w*a.w
             + b.x*b.x + b.y*b.y + b.z*b.z + b.w*b.w;
    #pragma unroll
    for (int o = 16; o > 0; o >>= 1) {
        s  += __shfl_xor_sync(0xffffffffu, s,  o);
        ss += __shfl_xor_sync(0xffffffffu, ss, o);
    }
    __shared__ float bs[8], bss[8];
    int w = t >> 5, l = t & 31;
    if (l == 0) { bs[w] = s; bss[w] = ss; }
    __syncthreads();
    float ts = 0.f, tss = 0.f;
    #pragma unroll
    for (int i = 0; i < 8; i++) { ts += bs[i]; tss += bss[i]; }
    float mean = ts * (1.0f / D_MOD);
    float var  = tss * (1.0f / D_MOD) - mean * mean;
    float inv  = rsqrtf(var + EPS);
    __half2* hp = (__half2*)(xh + (size_t)row * D_MOD);
    hp[t*2 + 0]   = __floats2half2_rn((a.x - mean) * inv, (a.y - mean) * inv);
    hp[t*2 + 1]   = __floats2half2_rn((a.z - mean) * inv, (a.w - mean) * inv);
    hp[512 + t*2] = __floats2half2_rn((b.x - mean) * inv, (b.y - mean) * inv);
    hp[513 + t*2] = __floats2half2_rn((b.z - mean) * inv, (b.w - mean) * inv);
}

// ---------------- transpose 4 weights W[K,N] -> Wt[N,K] fp16, one launch --------
__global__ void transpose4(const float* __restrict__ W0, const float* __restrict__ W1,
                           const float* __restrict__ W2, const float* __restrict__ W3,
                           __half* __restrict__ T0, __half* __restrict__ T1,
                           __half* __restrict__ T2, __half* __restrict__ T3) {
    const float* W = (blockIdx.z == 0) ? W0 : (blockIdx.z == 1) ? W1
                    : (blockIdx.z == 2) ? W2 : W3;
    __half* T = (blockIdx.z == 0) ? T0 : (blockIdx.z == 1) ? T1
               : (blockIdx.z == 2) ? T2 : T3;
    __shared__ float tile[32][33];
    int x = blockIdx.x * 32 + threadIdx.x;  // n
    int y = blockIdx.y * 32 + threadIdx.y;  // k
    #pragma unroll
    for (int i = 0; i < 4; i++)
        tile[threadIdx.y + i*8][threadIdx.x] = W[(size_t)(y + i*8) * D_MOD + x];
    __syncthreads();
    int nx = blockIdx.y * 32 + threadIdx.x;  // k
    int ny = blockIdx.x * 32 + threadIdx.y;  // n
    #pragma unroll
    for (int i = 0; i < 4; i++)
        T[(size_t)(ny + i*8) * D_MOD + nx] = __float2half_rn(tile[threadIdx.x][threadIdx.y + i*8]);
}

// ---------------- cast fp32 -> fp16 ----------------
__global__ void cast_h(const float* __restrict__ src, __half* __restrict__ dst, int n4) {
    int i = blockIdx.x * 256 + threadIdx.x;
    if (i < n4) {
        float4 v = ((const float4*)src)[i];
        __half2* d = (__half2*)dst;
        d[i*2 + 0] = __floats2half2_rn(v.x, v.y);
        d[i*2 + 1] = __floats2half2_rn(v.z, v.w);
    }
}

// ================ GEMM 128x128 tile, fp16 single product ================
// C[M,2048] = A[M,2048] @ Bt^T (+R).  8 warps 2x4, warp 64x32, BK=64, 2-stage.
#define NSTAGE 32
#define STG128 32768
#define G128_SMEM (2 * STG128)

__global__ __launch_bounds__(256)
void gemm128(const __half* __restrict__ A, const __half* __restrict__ B,
             float* __restrict__ C, const float* __restrict__ R) {
    extern __shared__ __align__(1024) char smem[];
    uint32_t sb = smem_u32(smem);
    int tid = threadIdx.x, wid = tid >> 5, lane = tid & 31;
    int wr = wid >> 2, wc = wid & 3;
    int rowBase = blockIdx.y * 128, colBase = blockIdx.x * 128;

    float acc[4][4][4];
    #pragma unroll
    for (int mi = 0; mi < 4; mi++)
        #pragma unroll
        for (int ni = 0; ni < 4; ni++)
            #pragma unroll
            for (int r = 0; r < 4; r++) acc[mi][ni][r] = 0.f;

    auto load_stage = [&](int s, int buf) {
        uint32_t so = sb + (uint32_t)buf * STG128;
        size_t kof = (size_t)s * 64;
        #pragma unroll
        for (int p = 0; p < 4; p++) {
            int chunk = tid + p * 256;
            int row = chunk >> 3, c = chunk & 7;
            uint32_t sw = swz((uint32_t)(row * 128 + c * 16));
            cpa16(so + sw,         A + (size_t)(rowBase + row) * 2048 + kof + c * 8);
            cpa16(so + 16384 + sw, B + (size_t)(colBase + row) * 2048 + kof + c * 8);
        }
        asm volatile("cp.async.commit_group;" ::: "memory");
    };

    load_stage(0, 0);
    load_stage(1, 1);

    for (int s = 0; s < NSTAGE; s++) {
        if (s + 2 < NSTAGE) asm volatile("cp.async.wait_group 1;" ::: "memory");
        else                asm volatile("cp.async.wait_group 0;" ::: "memory");
        __syncthreads();
        uint32_t so = sb + (uint32_t)(s & 1) * STG128;
        #pragma unroll
        for (int ks = 0; ks < 4; ks++) {
            uint32_t ah[4][4], bh[2][4];
            #pragma unroll
            for (int mi = 0; mi < 4; mi++) {
                int row = wr * 64 + mi * 16 + (lane & 15);
                int ch  = ks * 2 + (lane >> 4);
                ldsm4(so + swz((uint32_t)(row * 128 + ch * 16)), ah[mi]);
            }
            #pragma unroll
            for (int p = 0; p < 2; p++) {
                int row = wc * 32 + p * 16 + ((lane >> 4) << 3) + (lane & 7);
                int ch  = ks * 2 + ((lane >> 3) & 1);
                ldsm4(so + 16384 + swz((uint32_t)(row * 128 + ch * 16)), bh[p]);
            }
            #pragma unroll
            for (int mi = 0; mi < 4; mi++)
                #pragma unroll
                for (int ni = 0; ni < 4; ni++)
                    mma16816(acc[mi][ni], ah[mi], &bh[ni >> 1][(ni & 1) * 2]);
        }
        __syncthreads();
        if (s + 2 < NSTAGE) load_stage(s + 2, s & 1);
    }

    #pragma unroll
    for (int mi = 0; mi < 4; mi++)
        #pragma unroll
        for (int ni = 0; ni < 4; ni++) {
            int m0  = rowBase + wr * 64 + mi * 16 + (lane >> 2);
            int col = colBase + wc * 32 + ni * 8 + (lane & 3) * 2;
            size_t i0 = (size_t)m0 * 2048 + col;
            size_t i1 = i0 + (size_t)8 * 2048;
            float2 v0 = make_float2(acc[mi][ni][0], acc[mi][ni][1]);
            float2 v1 = make_float2(acc[mi][ni][2], acc[mi][ni][3]);
            if (R) {
                float2 r0 = *(const float2*)(R + i0);
                float2 r1 = *(const float2*)(R + i1);
                v0.x += r0.x; v0.y += r0.y;
                v1.x += r1.x; v1.y += r1.y;
            }
            *(float2*)(C + i0) = v0;
            *(float2*)(C + i1) = v1;
        }
}

// ================ GEMM 32x128 tile (for M=256 GEMMs) ================
// 8 warps, each warp: 32 rows x 16 cols. BK=64, 2-stage.
// stage: A 4KB @0, B 16KB @4096; stage stride 20480 (1KB-aligned bases).
#define STG32 20480
#define G32_SMEM (2 * STG32)

__global__ __launch_bounds__(256)
void gemm32(const __half* __restrict__ A, const __half* __restrict__ B,
            float* __restrict__ C, const float* __restrict__ R) {
    extern __shared__ __align__(1024) char smem[];
    uint32_t sb = smem_u32(smem);
    int tid = threadIdx.x, wid = tid >> 5, lane = tid & 31;
    int rowBase = blockIdx.y * 32, colBase = blockIdx.x * 128;

    float acc[2][2][4];
    #pragma unroll
    for (int mi = 0; mi < 2; mi++)
        #pragma unroll
        for (int ni = 0; ni < 2; ni++)
            #pragma unroll
            for (int r = 0; r < 4; r++) acc[mi][ni][r] = 0.f;

    auto load_stage = [&](int s, int buf) {
        uint32_t so = sb + (uint32_t)buf * STG32;
        size_t kof = (size_t)s * 64;
        {   // A: 32 rows x 8 chunks = 256
            int row = tid >> 3, c = tid & 7;
            uint32_t sw = swz((uint32_t)(row * 128 + c * 16));
            cpa16(so + sw, A + (size_t)(rowBase + row) * 2048 + kof + c * 8);
        }
        #pragma unroll
        for (int p = 0; p < 4; p++) {   // B: 128 rows x 8 chunks = 1024
            int chunk = tid + p * 256;
            int row = chunk >> 3, c = chunk & 7;
            uint32_t sw = swz((uint32_t)(row * 128 + c * 16));
            cpa16(so + 4096 + sw, B + (size_t)(colBase + row) * 2048 + kof + c * 8);
        }
        asm volatile("cp.async.commit_group;" ::: "memory");
    };

    load_stage(0, 0);
    load_stage(1, 1);

    for (int s = 0; s < NSTAGE; s++) {
        if (s + 2 < NSTAGE) asm volatile("cp.async.wait_group 1;" ::: "memory");
        else                asm volatile("cp.async.wait_group 0;" ::: "memory");
        __syncthreads();
        uint32_t so = sb + (uint32_t)(s & 1) * STG32;
        #pragma unroll
        for (int ks = 0; ks < 4; ks++) {
            uint32_t ah[2][4], bh[4];
            #pragma unroll
            for (int mi = 0; mi < 2; mi++) {
                int row = mi * 16 + (lane & 15);
                int ch  = ks * 2 + (lane >> 4);
                ldsm4(so + swz((uint32_t)(row * 128 + ch * 16)), ah[mi]);
            }
            {
                int row = wid * 16 + ((lane >> 4) << 3) + (lane & 7);
                int ch  = ks * 2 + ((lane >> 3) & 1);
                ldsm4(so + 4096 + swz((uint32_t)(row * 128 + ch * 16)), bh);
            }
            #pragma unroll
            for (int mi = 0; mi < 2; mi++)
                #pragma unroll
                for (int ni = 0; ni < 2; ni++)
                    mma16816(acc[mi][ni], ah[mi], &bh[ni * 2]);
        }
        __syncthreads();
        if (s + 2 < NSTAGE) load_stage(s + 2, s & 1);
    }

    #pragma unroll
    for (int mi = 0; mi < 2; mi++)
        #pragma unroll
        for (int ni = 0; ni < 2; ni++) {
            int m0  = rowBase + mi * 16 + (lane >> 2);
            int col = colBase + wid * 16 + ni * 8 + (lane & 3) * 2;
            size_t i0 = (size_t)m0 * 2048 + col;
            size_t i1 = i0 + (size_t)8 * 2048;
            float2 v0 = make_float2(acc[mi][ni][0], acc[mi][ni][1]);
            float2 v1 = make_float2(acc[mi][ni][2], acc[mi][ni][3]);
            if (R) {
                float2 r0 = *(const float2*)(R + i0);
                float2 r1 = *(const float2*)(R + i1);
                v0.x += r0.x; v0.y += r0.y;
                v1.x += r1.x; v1.y += r1.y;
            }
            *(float2*)(C + i0) = v0;
            *(float2*)(C + i1) = v1;
        }
}

// ---------------- per-head LayerNorm (DH=128) + cast to bf16 ----------------
__global__ void head_ln_cast(const float* __restrict__ raw,
                             __nv_bfloat16* __restrict__ out, int nseg) {
    int seg  = blockIdx.x * 8 + (threadIdx.x >> 5);
    int lane = threadIdx.x & 31;
    if (seg >= nseg) return;
    const float4* p = (const float4*)(raw + (size_t)seg * DHEAD);
    float4 v = p[lane];
    float s  = v.x + v.y + v.z + v.w;
    float ss = v.x*v.x + v.y*v.y + v.z*v.z + v.w*v.w;
    #pragma unroll
    for (int o = 16; o > 0; o >>= 1) {
        s  += __shfl_xor_sync(0xffffffffu, s,  o);
        ss += __shfl_xor_sync(0xffffffffu, ss, o);
    }
    float mean = s * (1.0f / DHEAD);
    float var  = ss * (1.0f / DHEAD) - mean * mean;
    float inv  = rsqrtf(var + EPS);
    __nv_bfloat162 o0 = __floats2bfloat162_rn((v.x - mean) * inv, (v.y - mean) * inv);
    __nv_bfloat162 o1 = __floats2bfloat162_rn((v.z - mean) * inv, (v.w - mean) * inv);
    __nv_bfloat162* op = (__nv_bfloat162*)(out + (size_t)seg * DHEAD);
    op[lane * 2 + 0] = o0;
    op[lane * 2 + 1] = o1;
}

// ---------------- sparse attention: block = (b, h), 16 q rows share keys ------
#define KPITCH 132
#define ATT_SMEM (16*128*4 + 16*128*4 + 128*KPITCH*2)

__global__ __launch_bounds__(128)
void attn2(const __nv_bfloat16* __restrict__ qbf, const __nv_bfloat16* __restrict__ kbf,
           const float* __restrict__ v, float* __restrict__ o) {
    extern __shared__ __align__(16) char asmem[];
    float* qs = (float*)asmem;                            // [16][128]
    float* ps = (float*)(asmem + 8192);                   // [16][128]
    __nv_bfloat16* ks = (__nv_bfloat16*)(asmem + 16384);  // [128][KPITCH]
    __shared__ float redm[64], reds[64];
    int b = blockIdx.x, h = blockIdx.y;
    int tid = threadIdx.x, w = tid >> 5, lane = tid & 31;

    for (int idx = tid; idx < 16 * 128; idx += 128) {
        int r = idx >> 7, d = idx & 127;
        qs[idx] = __bfloat162float(qbf[(size_t)(16*b + r) * D_MOD + h * DHEAD + d]);
    }
    for (int j = 0; j < 128; j++)
        ks[j * KPITCH + tid] = kbf[(size_t)(b + 16*j) * D_MOD + h * DHEAD + tid];
    __syncthreads();

    float s[16];
    #pragma unroll
    for (int r = 0; r < 16; r++) s[r] = 0.f;
    int j = tid;
    for (int d4 = 0; d4 < 32; d4++) {
        __nv_bfloat162 kk0 = *(const __nv_bfloat162*)(ks + j * KPITCH + d4 * 4);
        __nv_bfloat162 kk1 = *(const __nv_bfloat162*)(ks + j * KPITCH + d4 * 4 + 2);
        float2 k01 = __bfloat1622float2(kk0);
        float2 k23 = __bfloat1622float2(kk1);
        #pragma unroll
        for (int r = 0; r < 16; r++) {
            float4 qv = *(const float4*)(qs + r * 128 + d4 * 4);
            s[r] += qv.x * k01.x + qv.y * k01.y + qv.z * k23.x + qv.w * k23.y;
        }
    }
    const float SC = 0.08838834764831845f;
    #pragma unroll
    for (int r = 0; r < 16; r++) s[r] *= SC;

    #pragma unroll
    for (int r = 0; r < 16; r++) {
        float m = s[r];
        #pragma unroll
        for (int off = 16; off > 0; off >>= 1) m = fmaxf(m, __shfl_xor_sync(0xffffffffu, m, off));
        if (lane == 0) redm[r * 4 + w] = m;
    }
    __syncthreads();
    #pragma unroll
    for (int r = 0; r < 16; r++) {
        float mx = fmaxf(fmaxf(redm[r*4], redm[r*4+1]), fmaxf(redm[r*4+2], redm[r*4+3]));
        float p = __expf(s[r] - mx);
        ps[r * 128 + j] = p;
        float t = p;
        #pragma unroll
        for (int off = 16; off > 0; off >>= 1) t += __shfl_xor_sync(0xffffffffu, t, off);
        if (lane == 0) reds[r * 4 + w] = t;
    }
    __syncthreads();
    float inv[16];
    #pragma unroll
    for (int r = 0; r < 16; r++)
        inv[r] = 1.0f / fmaxf(reds[r*4] + reds[r*4+1] + reds[r*4+2] + reds[r*4+3], 1e-30f);

    float acc[16];
    #pragma unroll
    for (int r = 0; r < 16; r++) acc[r] = 0.f;
    int d = tid;
    const float* vp = v + h * DHEAD + d;
    for (int jj = 0; jj < 128; jj++) {
        float vv = vp[(size_t)(b + 16*jj) * D_MOD];
        #pragma unroll
        for (int r = 0; r < 16; r++) acc[r] += ps[r * 128 + jj] * vv;
    }
    #pragma unroll
    for (int r = 0; r < 16; r++)
        o[(size_t)(16*b + r) * D_MOD + h * DHEAD + d] = acc[r] * inv[r];
}

// ---------------- residual copy for rows >= 256 ----------------
__global__ void copy_tail(const float* __restrict__ x, float* __restrict__ out) {
    size_t i = (size_t)blockIdx.x * blockDim.x + threadIdx.x;
    const size_t count = (size_t)(N_TOK - NQ) * D_MOD / 4;
    if (i < count) {
        const float4* xs = (const float4*)(x + (size_t)NQ * D_MOD);
        float4* od = (float4*)(out + (size_t)NQ * D_MOD);
        od[i] = xs[i];
    }
}

extern "C" void kernel_launch(void* const* d_in, const int* in_sizes, int n_in,
                              void* d_out, int out_size) {
    const float* x  = (const float*)d_in[0];
    const float* Wq = (const float*)d_in[1];
    const float* Wk = (const float*)d_in[2];
    const float* Wv = (const float*)d_in[3];
    const float* Wo = (const float*)d_in[4];
    float* out = (float*)d_out;

    __half *xnh, *wqT, *wkT, *wvT, *woT, *oh;
    __nv_bfloat16 *kbf, *qbf;
    float *kraw, *v, *qraw, *o;
    cudaGetSymbolAddress((void**)&xnh,  g_xnh);
    cudaGetSymbolAddress((void**)&wqT,  g_wqT);
    cudaGetSymbolAddress((void**)&wkT,  g_wkT);
    cudaGetSymbolAddress((void**)&wvT,  g_wvT);
    cudaGetSymbolAddress((void**)&woT,  g_woT);
    cudaGetSymbolAddress((void**)&kraw, g_kraw);
    cudaGetSymbolAddress((void**)&v,    g_v);
    cudaGetSymbolAddress((void**)&qraw, g_qraw);
    cudaGetSymbolAddress((void**)&o,    g_o);
    cudaGetSymbolAddress((void**)&kbf,  g_kbf);
    cudaGetSymbolAddress((void**)&qbf,  g_qbf);
    cudaGetSymbolAddress((void**)&oh,   g_oh);

    cudaFuncSetAttribute(gemm128, cudaFuncAttributeMaxDynamicSharedMemorySize, G128_SMEM);
    cudaFuncSetAttribute(gemm32,  cudaFuncAttributeMaxDynamicSharedMemorySize, G32_SMEM);
    cudaFuncSetAttribute(attn2,   cudaFuncAttributeMaxDynamicSharedMemorySize, ATT_SMEM);

    // 1) LN -> fp16
    ln_f16<<<N_TOK, 256>>>(x, xnh);
    // 2) all weight transposes in one launch (fp16 out)
    transpose4<<<dim3(64, 64, 4), dim3(32, 8)>>>(Wq, Wk, Wv, Wo, wqT, wkT, wvT, woT);
    // 3) K projection -> head LN -> bf16
    gemm128<<<dim3(16, 16), 256, G128_SMEM>>>(xnh, wkT, kraw, nullptr);
    head_ln_cast<<<(N_TOK * NHEAD) / 8, 256>>>(kraw, kbf, N_TOK * NHEAD);
    // 4) V projection (fp32 out)
    gemm128<<<dim3(16, 16), 256, G128_SMEM>>>(xnh, wvT, v, nullptr);
    // 5) Q projection (rows 0..255) -> head LN -> bf16
    gemm32<<<dim3(16, 8), 256, G32_SMEM>>>(xnh, wqT, qraw, nullptr);
    head_ln_cast<<<(NQ * NHEAD) / 8, 256>>>(qraw, qbf, NQ * NHEAD);
    // 6) sparse attention
    attn2<<<dim3(16, 16), 128, ATT_SMEM>>>(qbf, kbf, v, o);
    // 7) out[0:256] = o @ Wo + x
    cast_h<<<(NQ * D_MOD / 4 + 255) / 256, 256>>>(o, oh, NQ * D_MOD / 4);
    gemm32<<<dim3(16, 8), 256, G32_SMEM>>>(oh, woT, out, x);
    // 8) out[256:] = x
    copy_tail<<<(int)(((size_t)(N_TOK - NQ) * D_MOD / 4 + 255) / 256), 256>>>(x, out);
}

// round 6
// speedup vs baseline: 7.8725x; 1.1567x over previous
#include <cuda_runtime.h>
#include <cuda_fp16.h>
#include <cuda_bf16.h>
#include <math.h>
#include <stdint.h>

// Problem constants
#define N_TOK 2048
#define D_MOD 2048
#define NHEAD 16
#define DHEAD 128
#define NQ    256
#define EPS   1e-5f

// ---------------- device scratch ----------------
__device__ __half         g_xnh [N_TOK * D_MOD];   // LN(x) fp16
__device__ __half         g_wqT [D_MOD * D_MOD];   // W^T fp16 (out-col major, contig k)
__device__ __half         g_wkT [D_MOD * D_MOD];
__device__ __half         g_wvT [D_MOD * D_MOD];
__device__ __half         g_woT [D_MOD * D_MOD];
__device__ float          g_v   [N_TOK * D_MOD];   // V projection fp32
__device__ __nv_bfloat16  g_kbf [N_TOK * D_MOD];   // head-LN(K) bf16
__device__ __nv_bfloat16  g_qbf [NQ * D_MOD];      // head-LN(Q) bf16
__device__ __half         g_oh  [NQ * D_MOD];      // attention out fp16

// ---------------- helpers ----------------
__device__ __forceinline__ uint32_t smem_u32(const void* p) {
    uint32_t a;
    asm("{ .reg .u64 t; cvta.to.shared.u64 t, %1; cvt.u32.u64 %0, t; }" : "=r"(a) : "l"(p));
    return a;
}
__device__ __forceinline__ void cpa16(uint32_t saddr, const void* gaddr) {
    asm volatile("cp.async.cg.shared.global [%0], [%1], 16;" :: "r"(saddr), "l"(gaddr));
}
__device__ __forceinline__ void ldsm4(uint32_t addr, uint32_t* r) {
    asm volatile("ldmatrix.sync.aligned.m8n8.x4.shared.b16 {%0,%1,%2,%3}, [%4];"
                 : "=r"(r[0]), "=r"(r[1]), "=r"(r[2]), "=r"(r[3]) : "r"(addr));
}
__device__ __forceinline__ void mma16816(float* c, const uint32_t* a, const uint32_t* b) {
    asm volatile("mma.sync.aligned.m16n8k16.row.col.f32.f16.f16.f32 "
        "{%0,%1,%2,%3}, {%4,%5,%6,%7}, {%8,%9}, {%0,%1,%2,%3};"
        : "+f"(c[0]), "+f"(c[1]), "+f"(c[2]), "+f"(c[3])
        : "r"(a[0]), "r"(a[1]), "r"(a[2]), "r"(a[3]), "r"(b[0]), "r"(b[1]));
}
__device__ __forceinline__ uint32_t swz(uint32_t off) {
    return off ^ ((off >> 3) & 0x70);
}

// ---------------- LayerNorm rows -> fp16 ----------------
__global__ void ln_f16(const float* __restrict__ x, __half* __restrict__ xh) {
    int row = blockIdx.x;
    int t = threadIdx.x;  // 256
    const float4* xr = (const float4*)(x + (size_t)row * D_MOD);
    float4 a = xr[t];
    float4 b = xr[t + 256];
    float s  = a.x + a.y + a.z + a.w + b.x + b.y + b.z + b.w;
    float ss = a.x*a.x + a.y*a.y + a.z*a.z + a.w*a.w
             + b.x*b.x + b.y*b.y + b.z*b.z + b.w*b.w;
    #pragma unroll
    for (int o = 16; o > 0; o >>= 1) {
        s  += __shfl_xor_sync(0xffffffffu, s,  o);
        ss += __shfl_xor_sync(0xffffffffu, ss, o);
    }
    __shared__ float bs[8], bss[8];
    int w = t >> 5, l = t & 31;
    if (l == 0) { bs[w] = s; bss[w] = ss; }
    __syncthreads();
    float ts = 0.f, tss = 0.f;
    #pragma unroll
    for (int i = 0; i < 8; i++) { ts += bs[i]; tss += bss[i]; }
    float mean = ts * (1.0f / D_MOD);
    float var  = tss * (1.0f / D_MOD) - mean * mean;
    float inv  = rsqrtf(var + EPS);
    __half2* hp = (__half2*)(xh + (size_t)row * D_MOD);
    hp[t*2 + 0]   = __floats2half2_rn((a.x - mean) * inv, (a.y - mean) * inv);
    hp[t*2 + 1]   = __floats2half2_rn((a.z - mean) * inv, (a.w - mean) * inv);
    hp[512 + t*2] = __floats2half2_rn((b.x - mean) * inv, (b.y - mean) * inv);
    hp[513 + t*2] = __floats2half2_rn((b.z - mean) * inv, (b.w - mean) * inv);
}

// ---------------- transpose 4 weights W[K,N] -> Wt[N,K] fp16, one launch --------
__global__ void transpose4(const float* __restrict__ W0, const float* __restrict__ W1,
                           const float* __restrict__ W2, const float* __restrict__ W3,
                           __half* __restrict__ T0, __half* __restrict__ T1,
                           __half* __restrict__ T2, __half* __restrict__ T3) {
    const float* W = (blockIdx.z == 0) ? W0 : (blockIdx.z == 1) ? W1
                    : (blockIdx.z == 2) ? W2 : W3;
    __half* T = (blockIdx.z == 0) ? T0 : (blockIdx.z == 1) ? T1
               : (blockIdx.z == 2) ? T2 : T3;
    __shared__ float tile[32][33];
    int x = blockIdx.x * 32 + threadIdx.x;  // n
    int y = blockIdx.y * 32 + threadIdx.y;  // k
    #pragma unroll
    for (int i = 0; i < 4; i++)
        tile[threadIdx.y + i*8][threadIdx.x] = W[(size_t)(y + i*8) * D_MOD + x];
    __syncthreads();
    int nx = blockIdx.y * 32 + threadIdx.x;  // k
    int ny = blockIdx.x * 32 + threadIdx.y;  // n
    #pragma unroll
    for (int i = 0; i < 4; i++)
        T[(size_t)(ny + i*8) * D_MOD + nx] = __float2half_rn(tile[threadIdx.x][threadIdx.y + i*8]);
}

// ================ fused projections: K / V / Q in one launch ================
// 128x128 CTA tile, 8 warps 2x4, warp 64x32, BK=64, 2-stage cp.async.
// modes: 0 = K (head-LN -> bf16), 1 = V (fp32), 2 = Q (head-LN -> bf16, M=256)
#define NSTAGE 32
#define STG128 32768
#define G128_SMEM (2 * STG128)

__global__ __launch_bounds__(256)
void proj_gemm(const __half* __restrict__ A,
               const __half* __restrict__ WK, const __half* __restrict__ WV,
               const __half* __restrict__ WQ,
               __nv_bfloat16* __restrict__ Kout, float* __restrict__ Vout,
               __nv_bfloat16* __restrict__ Qout) {
    extern __shared__ __align__(1024) char smem[];
    uint32_t sb = smem_u32(smem);
    int tid = threadIdx.x, wid = tid >> 5, lane = tid & 31;
    int wr = wid >> 2, wc = wid & 3;

    int bid = blockIdx.x, mode, tx, ty;
    const __half* B;
    if (bid < 256)      { mode = 0; tx = bid & 15; ty = bid >> 4; B = WK; }
    else if (bid < 512) { mode = 1; tx = (bid - 256) & 15; ty = (bid - 256) >> 4; B = WV; }
    else                { mode = 2; tx = (bid - 512) & 15; ty = (bid - 512) >> 4; B = WQ; }
    int rowBase = ty * 128, colBase = tx * 128;

    float acc[4][4][4];
    #pragma unroll
    for (int mi = 0; mi < 4; mi++)
        #pragma unroll
        for (int ni = 0; ni < 4; ni++)
            #pragma unroll
            for (int r = 0; r < 4; r++) acc[mi][ni][r] = 0.f;

    auto load_stage = [&](int s, int buf) {
        uint32_t so = sb + (uint32_t)buf * STG128;
        size_t kof = (size_t)s * 64;
        #pragma unroll
        for (int p = 0; p < 4; p++) {
            int chunk = tid + p * 256;
            int row = chunk >> 3, c = chunk & 7;
            uint32_t sw = swz((uint32_t)(row * 128 + c * 16));
            cpa16(so + sw,         A + (size_t)(rowBase + row) * 2048 + kof + c * 8);
            cpa16(so + 16384 + sw, B + (size_t)(colBase + row) * 2048 + kof + c * 8);
        }
        asm volatile("cp.async.commit_group;" ::: "memory");
    };

    load_stage(0, 0);
    load_stage(1, 1);

    for (int s = 0; s < NSTAGE; s++) {
        if (s + 2 < NSTAGE) asm volatile("cp.async.wait_group 1;" ::: "memory");
        else                asm volatile("cp.async.wait_group 0;" ::: "memory");
        __syncthreads();
        uint32_t so = sb + (uint32_t)(s & 1) * STG128;
        #pragma unroll
        for (int ks = 0; ks < 4; ks++) {
            uint32_t ah[4][4], bh[2][4];
            #pragma unroll
            for (int mi = 0; mi < 4; mi++) {
                int row = wr * 64 + mi * 16 + (lane & 15);
                int ch  = ks * 2 + (lane >> 4);
                ldsm4(so + swz((uint32_t)(row * 128 + ch * 16)), ah[mi]);
            }
            #pragma unroll
            for (int p = 0; p < 2; p++) {
                int row = wc * 32 + p * 16 + ((lane >> 4) << 3) + (lane & 7);
                int ch  = ks * 2 + ((lane >> 3) & 1);
                ldsm4(so + 16384 + swz((uint32_t)(row * 128 + ch * 16)), bh[p]);
            }
            #pragma unroll
            for (int mi = 0; mi < 4; mi++)
                #pragma unroll
                for (int ni = 0; ni < 4; ni++)
                    mma16816(acc[mi][ni], ah[mi], &bh[ni >> 1][(ni & 1) * 2]);
        }
        __syncthreads();
        if (s + 2 < NSTAGE) load_stage(s + 2, s & 1);
    }

    if (mode == 1) {
        // V: plain fp32 store
        #pragma unroll
        for (int mi = 0; mi < 4; mi++)
            #pragma unroll
            for (int ni = 0; ni < 4; ni++) {
                int m0  = rowBase + wr * 64 + mi * 16 + (lane >> 2);
                int col = colBase + wc * 32 + ni * 8 + (lane & 3) * 2;
                size_t i0 = (size_t)m0 * 2048 + col;
                size_t i1 = i0 + (size_t)8 * 2048;
                *(float2*)(Vout + i0) = make_float2(acc[mi][ni][0], acc[mi][ni][1]);
                *(float2*)(Vout + i1) = make_float2(acc[mi][ni][2], acc[mi][ni][3]);
            }
        return;
    }

    // K / Q: fused per-head LayerNorm over the 128 cols of this tile, -> bf16
    __nv_bfloat16* Out = (mode == 0) ? Kout : Qout;
    float sv[4][2], qv[4][2];
    #pragma unroll
    for (int mi = 0; mi < 4; mi++)
        #pragma unroll
        for (int h = 0; h < 2; h++) {
            float s = 0.f, q = 0.f;
            #pragma unroll
            for (int ni = 0; ni < 4; ni++) {
                float a0 = acc[mi][ni][h*2 + 0], a1 = acc[mi][ni][h*2 + 1];
                s += a0 + a1;
                q += a0*a0 + a1*a1;
            }
            // reduce across the 4 lanes of the quad (same output row)
            s += __shfl_xor_sync(0xffffffffu, s, 1);
            s += __shfl_xor_sync(0xffffffffu, s, 2);
            q += __shfl_xor_sync(0xffffffffu, q, 1);
            q += __shfl_xor_sync(0xffffffffu, q, 2);
            sv[mi][h] = s;
            qv[mi][h] = q;
        }
    __syncthreads();   // mainloop smem dead; reuse for cross-warp reduction
    float* sArr = (float*)smem;          // [4][128]
    float* qArr = ((float*)smem) + 512;  // [4][128]
    if ((lane & 3) == 0) {
        #pragma unroll
        for (int mi = 0; mi < 4; mi++)
            #pragma unroll
            for (int h = 0; h < 2; h++) {
                int row = wr * 64 + mi * 16 + (lane >> 2) + h * 8;
                sArr[wc * 128 + row] = sv[mi][h];
                qArr[wc * 128 + row] = qv[mi][h];
            }
    }
    __syncthreads();
    #pragma unroll
    for (int mi = 0; mi < 4; mi++)
        #pragma unroll
        for (int h = 0; h < 2; h++) {
            int row = wr * 64 + mi * 16 + (lane >> 2) + h * 8;
            float S = sArr[row] + sArr[128 + row] + sArr[256 + row] + sArr[384 + row];
            float Q = qArr[row] + qArr[128 + row] + qArr[256 + row] + qArr[384 + row];
            float mean = S * (1.0f / 128.0f);
            float var  = Q * (1.0f / 128.0f) - mean * mean;
            float inv  = rsqrtf(var + EPS);
            int m = rowBase + row;
            #pragma unroll
            for (int ni = 0; ni < 4; ni++) {
                int col = colBase + wc * 32 + ni * 8 + (lane & 3) * 2;
                float a0 = (acc[mi][ni][h*2 + 0] - mean) * inv;
                float a1 = (acc[mi][ni][h*2 + 1] - mean) * inv;
                *(__nv_bfloat162*)(Out + (size_t)m * 2048 + col) = __floats2bfloat162_rn(a0, a1);
            }
        }
}

// ================ GEMM 32x128 tile (Wo GEMM, M=256) ================
#define STG32 20480
#define G32_SMEM (2 * STG32)

__global__ __launch_bounds__(256)
void gemm32(const __half* __restrict__ A, const __half* __restrict__ B,
            float* __restrict__ C, const float* __restrict__ R) {
    extern __shared__ __align__(1024) char smem[];
    uint32_t sb = smem_u32(smem);
    int tid = threadIdx.x, wid = tid >> 5, lane = tid & 31;
    int rowBase = blockIdx.y * 32, colBase = blockIdx.x * 128;

    float acc[2][2][4];
    #pragma unroll
    for (int mi = 0; mi < 2; mi++)
        #pragma unroll
        for (int ni = 0; ni < 2; ni++)
            #pragma unroll
            for (int r = 0; r < 4; r++) acc[mi][ni][r] = 0.f;

    auto load_stage = [&](int s, int buf) {
        uint32_t so = sb + (uint32_t)buf * STG32;
        size_t kof = (size_t)s * 64;
        {
            int row = tid >> 3, c = tid & 7;
            uint32_t sw = swz((uint32_t)(row * 128 + c * 16));
            cpa16(so + sw, A + (size_t)(rowBase + row) * 2048 + kof + c * 8);
        }
        #pragma unroll
        for (int p = 0; p < 4; p++) {
            int chunk = tid + p * 256;
            int row = chunk >> 3, c = chunk & 7;
            uint32_t sw = swz((uint32_t)(row * 128 + c * 16));
            cpa16(so + 4096 + sw, B + (size_t)(colBase + row) * 2048 + kof + c * 8);
        }
        asm volatile("cp.async.commit_group;" ::: "memory");
    };

    load_stage(0, 0);
    load_stage(1, 1);

    for (int s = 0; s < NSTAGE; s++) {
        if (s + 2 < NSTAGE) asm volatile("cp.async.wait_group 1;" ::: "memory");
        else                asm volatile("cp.async.wait_group 0;" ::: "memory");
        __syncthreads();
        uint32_t so = sb + (uint32_t)(s & 1) * STG32;
        #pragma unroll
        for (int ks = 0; ks < 4; ks++) {
            uint32_t ah[2][4], bh[4];
            #pragma unroll
            for (int mi = 0; mi < 2; mi++) {
                int row = mi * 16 + (lane & 15);
                int ch  = ks * 2 + (lane >> 4);
                ldsm4(so + swz((uint32_t)(row * 128 + ch * 16)), ah[mi]);
            }
            {
                int row = wid * 16 + ((lane >> 4) << 3) + (lane & 7);
                int ch  = ks * 2 + ((lane >> 3) & 1);
                ldsm4(so + 4096 + swz((uint32_t)(row * 128 + ch * 16)), bh);
            }
            #pragma unroll
            for (int mi = 0; mi < 2; mi++)
                #pragma unroll
                for (int ni = 0; ni < 2; ni++)
                    mma16816(acc[mi][ni], ah[mi], &bh[ni * 2]);
        }
        __syncthreads();
        if (s + 2 < NSTAGE) load_stage(s + 2, s & 1);
    }

    #pragma unroll
    for (int mi = 0; mi < 2; mi++)
        #pragma unroll
        for (int ni = 0; ni < 2; ni++) {
            int m0  = rowBase + mi * 16 + (lane >> 2);
            int col = colBase + wid * 16 + ni * 8 + (lane & 3) * 2;
            size_t i0 = (size_t)m0 * 2048 + col;
            size_t i1 = i0 + (size_t)8 * 2048;
            float2 v0 = make_float2(acc[mi][ni][0], acc[mi][ni][1]);
            float2 v1 = make_float2(acc[mi][ni][2], acc[mi][ni][3]);
            if (R) {
                float2 r0 = *(const float2*)(R + i0);
                float2 r1 = *(const float2*)(R + i1);
                v0.x += r0.x; v0.y += r0.y;
                v1.x += r1.x; v1.y += r1.y;
            }
            *(float2*)(C + i0) = v0;
            *(float2*)(C + i1) = v1;
        }
}

// ---------------- sparse attention: block = (b, h), 16 q rows share keys ------
#define KPITCH 132
#define ATT_SMEM (16*128*4 + 16*128*4 + 128*KPITCH*2)

__global__ __launch_bounds__(128)
void attn2(const __nv_bfloat16* __restrict__ qbf, const __nv_bfloat16* __restrict__ kbf,
           const float* __restrict__ v, __half* __restrict__ o) {
    extern __shared__ __align__(16) char asmem[];
    float* qs = (float*)asmem;                            // [16][128]
    float* ps = (float*)(asmem + 8192);                   // [16][128]
    __nv_bfloat16* ks = (__nv_bfloat16*)(asmem + 16384);  // [128][KPITCH]
    __shared__ float redm[64], reds[64];
    int b = blockIdx.x, h = blockIdx.y;
    int tid = threadIdx.x, w = tid >> 5, lane = tid & 31;

    for (int idx = tid; idx < 16 * 128; idx += 128) {
        int r = idx >> 7, d = idx & 127;
        qs[idx] = __bfloat162float(qbf[(size_t)(16*b + r) * D_MOD + h * DHEAD + d]);
    }
    for (int j = 0; j < 128; j++)
        ks[j * KPITCH + tid] = kbf[(size_t)(b + 16*j) * D_MOD + h * DHEAD + tid];
    __syncthreads();

    float s[16];
    #pragma unroll
    for (int r = 0; r < 16; r++) s[r] = 0.f;
    int j = tid;
    for (int d4 = 0; d4 < 32; d4++) {
        __nv_bfloat162 kk0 = *(const __nv_bfloat162*)(ks + j * KPITCH + d4 * 4);
        __nv_bfloat162 kk1 = *(const __nv_bfloat162*)(ks + j * KPITCH + d4 * 4 + 2);
        float2 k01 = __bfloat1622float2(kk0);
        float2 k23 = __bfloat1622float2(kk1);
        #pragma unroll
        for (int r = 0; r < 16; r++) {
            float4 qv = *(const float4*)(qs + r * 128 + d4 * 4);
            s[r] += qv.x * k01.x + qv.y * k01.y + qv.z * k23.x + qv.w * k23.y;
        }
    }
    const float SC = 0.08838834764831845f;
    #pragma unroll
    for (int r = 0; r < 16; r++) s[r] *= SC;

    #pragma unroll
    for (int r = 0; r < 16; r++) {
        float m = s[r];
        #pragma unroll
        for (int off = 16; off > 0; off >>= 1) m = fmaxf(m, __shfl_xor_sync(0xffffffffu, m, off));
        if (lane == 0) redm[r * 4 + w] = m;
    }
    __syncthreads();
    #pragma unroll
    for (int r = 0; r < 16; r++) {
        float mx = fmaxf(fmaxf(redm[r*4], redm[r*4+1]), fmaxf(redm[r*4+2], redm[r*4+3]));
        float p = __expf(s[r] - mx);
        ps[r * 128 + j] = p;
        float t = p;
        #pragma unroll
        for (int off = 16; off > 0; off >>= 1) t += __shfl_xor_sync(0xffffffffu, t, off);
        if (lane == 0) reds[r * 4 + w] = t;
    }
    __syncthreads();
    float inv[16];
    #pragma unroll
    for (int r = 0; r < 16; r++)
        inv[r] = 1.0f / fmaxf(reds[r*4] + reds[r*4+1] + reds[r*4+2] + reds[r*4+3], 1e-30f);

    float acc[16];
    #pragma unroll
    for (int r = 0; r < 16; r++) acc[r] = 0.f;
    int d = tid;
    const float* vp = v + h * DHEAD + d;
    for (int jj = 0; jj < 128; jj++) {
        float vv = vp[(size_t)(b + 16*jj) * D_MOD];
        #pragma unroll
        for (int r = 0; r < 16; r++) acc[r] += ps[r * 128 + jj] * vv;
    }
    #pragma unroll
    for (int r = 0; r < 16; r++)
        o[(size_t)(16*b + r) * D_MOD + h * DHEAD + d] = __float2half_rn(acc[r] * inv[r]);
}

// ---------------- residual copy for rows >= 256 ----------------
__global__ void copy_tail(const float* __restrict__ x, float* __restrict__ out) {
    size_t i = (size_t)blockIdx.x * blockDim.x + threadIdx.x;
    const size_t count = (size_t)(N_TOK - NQ) * D_MOD / 4;
    if (i < count) {
        const float4* xs = (const float4*)(x + (size_t)NQ * D_MOD);
        float4* od = (float4*)(out + (size_t)NQ * D_MOD);
        od[i] = xs[i];
    }
}

extern "C" void kernel_launch(void* const* d_in, const int* in_sizes, int n_in,
                              void* d_out, int out_size) {
    const float* x  = (const float*)d_in[0];
    const float* Wq = (const float*)d_in[1];
    const float* Wk = (const float*)d_in[2];
    const float* Wv = (const float*)d_in[3];
    const float* Wo = (const float*)d_in[4];
    float* out = (float*)d_out;

    __half *xnh, *wqT, *wkT, *wvT, *woT, *oh;
    __nv_bfloat16 *kbf, *qbf;
    float *v;
    cudaGetSymbolAddress((void**)&xnh,  g_xnh);
    cudaGetSymbolAddress((void**)&wqT,  g_wqT);
    cudaGetSymbolAddress((void**)&wkT,  g_wkT);
    cudaGetSymbolAddress((void**)&wvT,  g_wvT);
    cudaGetSymbolAddress((void**)&woT,  g_woT);
    cudaGetSymbolAddress((void**)&v,    g_v);
    cudaGetSymbolAddress((void**)&kbf,  g_kbf);
    cudaGetSymbolAddress((void**)&qbf,  g_qbf);
    cudaGetSymbolAddress((void**)&oh,   g_oh);

    cudaFuncSetAttribute(proj_gemm, cudaFuncAttributeMaxDynamicSharedMemorySize, G128_SMEM);
    cudaFuncSetAttribute(gemm32,    cudaFuncAttributeMaxDynamicSharedMemorySize, G32_SMEM);
    cudaFuncSetAttribute(attn2,     cudaFuncAttributeMaxDynamicSharedMemorySize, ATT_SMEM);

    // 1) LN -> fp16
    ln_f16<<<N_TOK, 256>>>(x, xnh);
    // 2) all weight transposes in one launch (fp16 out)
    transpose4<<<dim3(64, 64, 4), dim3(32, 8)>>>(Wq, Wk, Wv, Wo, wqT, wkT, wvT, woT);
    // 3) K + V + Q projections fused (K/Q with fused head-LN -> bf16)
    proj_gemm<<<544, 256, G128_SMEM>>>(xnh, wkT, wvT, wqT, kbf, v, qbf);
    // 4) sparse attention -> fp16
    attn2<<<dim3(16, 16), 128, ATT_SMEM>>>(qbf, kbf, v, oh);
    // 5) out[0:256] = o @ Wo + x
    gemm32<<<dim3(16, 8), 256, G32_SMEM>>>(oh, woT, out, x);
    // 6) out[256:] = x
    copy_tail<<<(int)(((size_t)(N_TOK - NQ) * D_MOD / 4 + 255) / 256), 256>>>(x, out);
}

// round 7
// speedup vs baseline: 8.5427x; 1.0851x over previous
#include <cuda_runtime.h>
#include <cuda_fp16.h>
#include <cuda_bf16.h>
#include <math.h>
#include <stdint.h>

// Problem constants
#define N_TOK 2048
#define D_MOD 2048
#define NHEAD 16
#define DHEAD 128
#define NQ    256
#define EPS   1e-5f

// ---------------- device scratch ----------------
__device__ __half         g_xnh [N_TOK * D_MOD];   // LN(x) fp16
__device__ __half         g_wqT [D_MOD * D_MOD];   // W^T fp16 (out-col major, contig k)
__device__ __half         g_wkT [D_MOD * D_MOD];
__device__ __half         g_wvT [D_MOD * D_MOD];
__device__ __half         g_woT [D_MOD * D_MOD];
__device__ float          g_v   [N_TOK * D_MOD];   // V projection fp32
__device__ __nv_bfloat16  g_kbf [N_TOK * D_MOD];   // head-LN(K) bf16
__device__ __nv_bfloat16  g_qbf [NQ * D_MOD];      // head-LN(Q) bf16
__device__ __half         g_oh  [NQ * D_MOD];      // attention out fp16

// ---------------- helpers ----------------
__device__ __forceinline__ uint32_t smem_u32(const void* p) {
    uint32_t a;
    asm("{ .reg .u64 t; cvta.to.shared.u64 t, %1; cvt.u32.u64 %0, t; }" : "=r"(a) : "l"(p));
    return a;
}
__device__ __forceinline__ void cpa16(uint32_t saddr, const void* gaddr) {
    asm volatile("cp.async.cg.shared.global [%0], [%1], 16;" :: "r"(saddr), "l"(gaddr));
}
__device__ __forceinline__ void ldsm4(uint32_t addr, uint32_t* r) {
    asm volatile("ldmatrix.sync.aligned.m8n8.x4.shared.b16 {%0,%1,%2,%3}, [%4];"
                 : "=r"(r[0]), "=r"(r[1]), "=r"(r[2]), "=r"(r[3]) : "r"(addr));
}
__device__ __forceinline__ void mma16816(float* c, const uint32_t* a, const uint32_t* b) {
    asm volatile("mma.sync.aligned.m16n8k16.row.col.f32.f16.f16.f32 "
        "{%0,%1,%2,%3}, {%4,%5,%6,%7}, {%8,%9}, {%0,%1,%2,%3};"
        : "+f"(c[0]), "+f"(c[1]), "+f"(c[2]), "+f"(c[3])
        : "r"(a[0]), "r"(a[1]), "r"(a[2]), "r"(a[3]), "r"(b[0]), "r"(b[1]));
}
__device__ __forceinline__ uint32_t swz(uint32_t off) {
    return off ^ ((off >> 3) & 0x70);
}

// ================ prep: LN(x)->fp16  +  4 weight transposes, one launch ==========
// blocks [0, 2048)        : LayerNorm rows
// blocks [2048, 2048+4*4096): transpose tiles (which = (bid-2048)>>12)
__global__ __launch_bounds__(256)
void prep(const float* __restrict__ x, __half* __restrict__ xh,
          const float* __restrict__ W0, const float* __restrict__ W1,
          const float* __restrict__ W2, const float* __restrict__ W3,
          __half* __restrict__ T0, __half* __restrict__ T1,
          __half* __restrict__ T2, __half* __restrict__ T3) {
    __shared__ float tile[32][33];   // used by transpose branch
    __shared__ float bs[8], bss[8];  // used by LN branch
    int bid = blockIdx.x;
    int tid = threadIdx.x;

    if (bid < 2048) {
        // ---- LayerNorm row -> fp16 ----
        int row = bid;
        const float4* xr = (const float4*)(x + (size_t)row * D_MOD);
        float4 a = xr[tid];
        float4 b = xr[tid + 256];
        float s  = a.x + a.y + a.z + a.w + b.x + b.y + b.z + b.w;
        float ss = a.x*a.x + a.y*a.y + a.z*a.z + a.w*a.w
                 + b.x*b.x + b.y*b.y + b.z*b.z + b.w*b.w;
        #pragma unroll
        for (int o = 16; o > 0; o >>= 1) {
            s  += __shfl_xor_sync(0xffffffffu, s,  o);
            ss += __shfl_xor_sync(0xffffffffu, ss, o);
        }
        int w = tid >> 5, l = tid & 31;
        if (l == 0) { bs[w] = s; bss[w] = ss; }
        __syncthreads();
        float ts = 0.f, tss = 0.f;
        #pragma unroll
        for (int i = 0; i < 8; i++) { ts += bs[i]; tss += bss[i]; }
        float mean = ts * (1.0f / D_MOD);
        float var  = tss * (1.0f / D_MOD) - mean * mean;
        float inv  = rsqrtf(var + EPS);
        __half2* hp = (__half2*)(xh + (size_t)row * D_MOD);
        hp[tid*2 + 0]   = __floats2half2_rn((a.x - mean) * inv, (a.y - mean) * inv);
        hp[tid*2 + 1]   = __floats2half2_rn((a.z - mean) * inv, (a.w - mean) * inv);
        hp[512 + tid*2] = __floats2half2_rn((b.x - mean) * inv, (b.y - mean) * inv);
        hp[513 + tid*2] = __floats2half2_rn((b.z - mean) * inv, (b.w - mean) * inv);
    } else {
        // ---- transpose one 32x32 tile of one weight ----
        int t = bid - 2048;
        int which = t >> 12;
        int rem = t & 4095;
        int bx = rem & 63, by = rem >> 6;
        const float* W = (which == 0) ? W0 : (which == 1) ? W1 : (which == 2) ? W2 : W3;
        __half* T = (which == 0) ? T0 : (which == 1) ? T1 : (which == 2) ? T2 : T3;
        int tx = tid & 31, ty = tid >> 5;   // 32 x 8
        int xcol = bx * 32 + tx;            // n
        int yrow = by * 32 + ty;            // k
        #pragma unroll
        for (int i = 0; i < 4; i++)
            tile[ty + i*8][tx] = W[(size_t)(yrow + i*8) * D_MOD + xcol];
        __syncthreads();
        int nx = by * 32 + tx;  // k
        int ny = bx * 32 + ty;  // n
        #pragma unroll
        for (int i = 0; i < 4; i++)
            T[(size_t)(ny + i*8) * D_MOD + nx] = __float2half_rn(tile[tx][ty + i*8]);
    }
}

// ================ fused projections: K / V / Q in one launch ================
// 128x128 CTA tile, 8 warps 2x4, warp 64x32, BK=64, 2-stage cp.async.
// modes: 0 = K (head-LN -> bf16), 1 = V (fp32), 2 = Q (head-LN -> bf16, M=256)
#define NSTAGE 32
#define STG128 32768
#define G128_SMEM (2 * STG128)

__global__ __launch_bounds__(256)
void proj_gemm(const __half* __restrict__ A,
               const __half* __restrict__ WK, const __half* __restrict__ WV,
               const __half* __restrict__ WQ,
               __nv_bfloat16* __restrict__ Kout, float* __restrict__ Vout,
               __nv_bfloat16* __restrict__ Qout) {
    extern __shared__ __align__(1024) char smem[];
    uint32_t sb = smem_u32(smem);
    int tid = threadIdx.x, wid = tid >> 5, lane = tid & 31;
    int wr = wid >> 2, wc = wid & 3;

    int bid = blockIdx.x, mode, tx, ty;
    const __half* B;
    if (bid < 256)      { mode = 0; tx = bid & 15; ty = bid >> 4; B = WK; }
    else if (bid < 512) { mode = 1; tx = (bid - 256) & 15; ty = (bid - 256) >> 4; B = WV; }
    else                { mode = 2; tx = (bid - 512) & 15; ty = (bid - 512) >> 4; B = WQ; }
    int rowBase = ty * 128, colBase = tx * 128;

    float acc[4][4][4];
    #pragma unroll
    for (int mi = 0; mi < 4; mi++)
        #pragma unroll
        for (int ni = 0; ni < 4; ni++)
            #pragma unroll
            for (int r = 0; r < 4; r++) acc[mi][ni][r] = 0.f;

    auto load_stage = [&](int s, int buf) {
        uint32_t so = sb + (uint32_t)buf * STG128;
        size_t kof = (size_t)s * 64;
        #pragma unroll
        for (int p = 0; p < 4; p++) {
            int chunk = tid + p * 256;
            int row = chunk >> 3, c = chunk & 7;
            uint32_t sw = swz((uint32_t)(row * 128 + c * 16));
            cpa16(so + sw,         A + (size_t)(rowBase + row) * 2048 + kof + c * 8);
            cpa16(so + 16384 + sw, B + (size_t)(colBase + row) * 2048 + kof + c * 8);
        }
        asm volatile("cp.async.commit_group;" ::: "memory");
    };

    load_stage(0, 0);
    load_stage(1, 1);

    for (int s = 0; s < NSTAGE; s++) {
        if (s + 2 < NSTAGE) asm volatile("cp.async.wait_group 1;" ::: "memory");
        else                asm volatile("cp.async.wait_group 0;" ::: "memory");
        __syncthreads();
        uint32_t so = sb + (uint32_t)(s & 1) * STG128;
        #pragma unroll
        for (int ks = 0; ks < 4; ks++) {
            uint32_t ah[4][4], bh[2][4];
            #pragma unroll
            for (int mi = 0; mi < 4; mi++) {
                int row = wr * 64 + mi * 16 + (lane & 15);
                int ch  = ks * 2 + (lane >> 4);
                ldsm4(so + swz((uint32_t)(row * 128 + ch * 16)), ah[mi]);
            }
            #pragma unroll
            for (int p = 0; p < 2; p++) {
                int row = wc * 32 + p * 16 + ((lane >> 4) << 3) + (lane & 7);
                int ch  = ks * 2 + ((lane >> 3) & 1);
                ldsm4(so + 16384 + swz((uint32_t)(row * 128 + ch * 16)), bh[p]);
            }
            #pragma unroll
            for (int mi = 0; mi < 4; mi++)
                #pragma unroll
                for (int ni = 0; ni < 4; ni++)
                    mma16816(acc[mi][ni], ah[mi], &bh[ni >> 1][(ni & 1) * 2]);
        }
        __syncthreads();
        if (s + 2 < NSTAGE) load_stage(s + 2, s & 1);
    }

    if (mode == 1) {
        #pragma unroll
        for (int mi = 0; mi < 4; mi++)
            #pragma unroll
            for (int ni = 0; ni < 4; ni++) {
                int m0  = rowBase + wr * 64 + mi * 16 + (lane >> 2);
                int col = colBase + wc * 32 + ni * 8 + (lane & 3) * 2;
                size_t i0 = (size_t)m0 * 2048 + col;
                size_t i1 = i0 + (size_t)8 * 2048;
                *(float2*)(Vout + i0) = make_float2(acc[mi][ni][0], acc[mi][ni][1]);
                *(float2*)(Vout + i1) = make_float2(acc[mi][ni][2], acc[mi][ni][3]);
            }
        return;
    }

    // K / Q: fused per-head LayerNorm over the 128 cols of this tile, -> bf16
    __nv_bfloat16* Out = (mode == 0) ? Kout : Qout;
    float sv[4][2], qv[4][2];
    #pragma unroll
    for (int mi = 0; mi < 4; mi++)
        #pragma unroll
        for (int h = 0; h < 2; h++) {
            float s = 0.f, q = 0.f;
            #pragma unroll
            for (int ni = 0; ni < 4; ni++) {
                float a0 = acc[mi][ni][h*2 + 0], a1 = acc[mi][ni][h*2 + 1];
                s += a0 + a1;
                q += a0*a0 + a1*a1;
            }
            s += __shfl_xor_sync(0xffffffffu, s, 1);
            s += __shfl_xor_sync(0xffffffffu, s, 2);
            q += __shfl_xor_sync(0xffffffffu, q, 1);
            q += __shfl_xor_sync(0xffffffffu, q, 2);
            sv[mi][h] = s;
            qv[mi][h] = q;
        }
    __syncthreads();
    float* sArr = (float*)smem;
    float* qArr = ((float*)smem) + 512;
    if ((lane & 3) == 0) {
        #pragma unroll
        for (int mi = 0; mi < 4; mi++)
            #pragma unroll
            for (int h = 0; h < 2; h++) {
                int row = wr * 64 + mi * 16 + (lane >> 2) + h * 8;
                sArr[wc * 128 + row] = sv[mi][h];
                qArr[wc * 128 + row] = qv[mi][h];
            }
    }
    __syncthreads();
    #pragma unroll
    for (int mi = 0; mi < 4; mi++)
        #pragma unroll
        for (int h = 0; h < 2; h++) {
            int row = wr * 64 + mi * 16 + (lane >> 2) + h * 8;
            float S = sArr[row] + sArr[128 + row] + sArr[256 + row] + sArr[384 + row];
            float Q = qArr[row] + qArr[128 + row] + qArr[256 + row] + qArr[384 + row];
            float mean = S * (1.0f / 128.0f);
            float var  = Q * (1.0f / 128.0f) - mean * mean;
            float inv  = rsqrtf(var + EPS);
            int m = rowBase + row;
            #pragma unroll
            for (int ni = 0; ni < 4; ni++) {
                int col = colBase + wc * 32 + ni * 8 + (lane & 3) * 2;
                float a0 = (acc[mi][ni][h*2 + 0] - mean) * inv;
                float a1 = (acc[mi][ni][h*2 + 1] - mean) * inv;
                *(__nv_bfloat162*)(Out + (size_t)m * 2048 + col) = __floats2bfloat162_rn(a0, a1);
            }
        }
}

// ================ sparse attention v3: block=(b,h), 256 threads ================
// keys m = b + 16j.  K, V, Q staged in smem with vectorized high-MLP loads.
// smem: qs[16][128] f32 | ps[16][128] f32 | vs[128][128] f32 | ks[128][132] bf16
#define KROWB 264   // 132 bf16 per K row
#define ATT3_SMEM (8192 + 8192 + 65536 + 128 * KROWB)

__global__ __launch_bounds__(256)
void attn3(const __nv_bfloat16* __restrict__ qbf, const __nv_bfloat16* __restrict__ kbf,
           const float* __restrict__ v, __half* __restrict__ o) {
    extern __shared__ __align__(16) char asmem[];
    float* qs = (float*)asmem;                     // [16][128]
    float* ps = qs + 2048;                         // [16][128]
    float* vs = ps + 2048;                         // [128][128]
    char*  ks = asmem + 8192 + 8192 + 65536;       // [128][264B]
    __shared__ float redm[16][4], reds[16][4];
    int b = blockIdx.x, h = blockIdx.y;
    int tid = threadIdx.x, lane = tid & 31;
    int w4 = (tid >> 5) & 3;

    // ---- Q: 256 threads x 1 uint4 (8 bf16) ----
    {
        int r = tid >> 4, c = tid & 15;
        uint4 qv = *(const uint4*)(qbf + (size_t)(16*b + r) * D_MOD + h * DHEAD + c * 8);
        const __nv_bfloat162* qb = (const __nv_bfloat162*)&qv;
        float2 f0 = __bfloat1622float2(qb[0]);
        float2 f1 = __bfloat1622float2(qb[1]);
        float2 f2 = __bfloat1622float2(qb[2]);
        float2 f3 = __bfloat1622float2(qb[3]);
        *(float4*)(qs + r * 128 + c * 8)     = make_float4(f0.x, f0.y, f1.x, f1.y);
        *(float4*)(qs + r * 128 + c * 8 + 4) = make_float4(f2.x, f2.y, f3.x, f3.y);
    }
    // ---- K: 16 independent 8B loads per thread ----
    #pragma unroll
    for (int p = 0; p < 16; p++) {
        int idx = tid + p * 256;
        int j = idx >> 5, c = idx & 31;
        uint2 kk = *(const uint2*)(kbf + (size_t)(b + 16*j) * D_MOD + h * DHEAD + c * 4);
        *(uint2*)(ks + j * KROWB + c * 8) = kk;
    }
    // ---- V: 16 independent 16B loads per thread (fp32, exact) ----
    #pragma unroll
    for (int p = 0; p < 16; p++) {
        int idx = tid + p * 256;
        int j = idx >> 5, c = idx & 31;
        float4 vv = *(const float4*)(v + (size_t)(b + 16*j) * D_MOD + h * DHEAD + c * 4);
        *(float4*)(vs + j * 128 + c * 4) = vv;
    }
    __syncthreads();

    // ---- scores: thread = (j, rhalf); 8 rows each ----
    int j = tid & 127, rh = tid >> 7;
    float s[8];
    #pragma unroll
    for (int r8 = 0; r8 < 8; r8++) s[r8] = 0.f;
    #pragma unroll 4
    for (int d4 = 0; d4 < 32; d4++) {
        uint2 kk = *(const uint2*)(ks + j * KROWB + d4 * 8);
        float2 k01 = __bfloat1622float2(*(const __nv_bfloat162*)&kk.x);
        float2 k23 = __bfloat1622float2(*(const __nv_bfloat162*)&kk.y);
        #pragma unroll
        for (int r8 = 0; r8 < 8; r8++) {
            float4 qv = *(const float4*)(qs + (rh * 8 + r8) * 128 + d4 * 4);
            s[r8] += qv.x * k01.x + qv.y * k01.y + qv.z * k23.x + qv.w * k23.y;
        }
    }
    const float SC = 0.08838834764831845f;  // 1/sqrt(128)
    #pragma unroll
    for (int r8 = 0; r8 < 8; r8++) s[r8] *= SC;

    // ---- softmax over 128 j (4 warps per rhalf) ----
    #pragma unroll
    for (int r8 = 0; r8 < 8; r8++) {
        float m = s[r8];
        #pragma unroll
        for (int off = 16; off > 0; off >>= 1) m = fmaxf(m, __shfl_xor_sync(0xffffffffu, m, off));
        if (lane == 0) redm[rh * 8 + r8][w4] = m;
    }
    __syncthreads();
    #pragma unroll
    for (int r8 = 0; r8 < 8; r8++) {
        int r = rh * 8 + r8;
        float mx = fmaxf(fmaxf(redm[r][0], redm[r][1]), fmaxf(redm[r][2], redm[r][3]));
        float p = __expf(s[r8] - mx);
        ps[r * 128 + j] = p;
        float t = p;
        #pragma unroll
        for (int off = 16; off > 0; off >>= 1) t += __shfl_xor_sync(0xffffffffu, t, off);
        if (lane == 0) reds[r][w4] = t;
    }
    __syncthreads();
    float invr[8];
    #pragma unroll
    for (int r8 = 0; r8 < 8; r8++) {
        int r = rh * 8 + r8;
        invr[r8] = 1.0f / fmaxf(reds[r][0] + reds[r][1] + reds[r][2] + reds[r][3], 1e-30f);
    }

    // ---- output: thread = (d, rhalf); V + P from smem ----
    int d = tid & 127;
    float acc[8];
    #pragma unroll
    for (int r8 = 0; r8 < 8; r8++) acc[r8] = 0.f;
    #pragma unroll 4
    for (int jj = 0; jj < 128; jj++) {
        float vv = vs[jj * 128 + d];
        #pragma unroll
        for (int r8 = 0; r8 < 8; r8++)
            acc[r8] += ps[(rh * 8 + r8) * 128 + jj] * vv;
    }
    #pragma unroll
    for (int r8 = 0; r8 < 8; r8++) {
        int r = rh * 8 + r8;
        o[(size_t)(16*b + r) * D_MOD + h * DHEAD + d] = __float2half_rn(acc[r8] * invr[r8]);
    }
}

// ================ Wo GEMM (M=256, 32x128 tiles) + tail residual copy, one launch ==
// blocks [0,128): GEMM tiles; blocks [128,256): grid-stride copy of rows >= 256.
#define STG32 20480
#define G32_SMEM (2 * STG32)

__global__ __launch_bounds__(256)
void gemm32copy(const __half* __restrict__ A, const __half* __restrict__ B,
                float* __restrict__ C, const float* __restrict__ R,
                const float* __restrict__ x) {
    int bid = blockIdx.x;
    int tid = threadIdx.x;

    if (bid >= 128) {
        // ---- tail copy: out[256:] = x[256:] ----
        const size_t count = (size_t)(N_TOK - NQ) * D_MOD / 4;
        const float4* xs = (const float4*)(x + (size_t)NQ * D_MOD);
        float4* od = (float4*)(C + (size_t)NQ * D_MOD);
        for (size_t i = (size_t)(bid - 128) * 256 + tid; i < count; i += 128 * 256)
            od[i] = xs[i];
        return;
    }

    extern __shared__ __align__(1024) char smem[];
    uint32_t sb = smem_u32(smem);
    int wid = tid >> 5, lane = tid & 31;
    int rowBase = (bid >> 4) * 32, colBase = (bid & 15) * 128;

    float acc[2][2][4];
    #pragma unroll
    for (int mi = 0; mi < 2; mi++)
        #pragma unroll
        for (int ni = 0; ni < 2; ni++)
            #pragma unroll
            for (int r = 0; r < 4; r++) acc[mi][ni][r] = 0.f;

    auto load_stage = [&](int s, int buf) {
        uint32_t so = sb + (uint32_t)buf * STG32;
        size_t kof = (size_t)s * 64;
        {
            int row = tid >> 3, c = tid & 7;
            uint32_t sw = swz((uint32_t)(row * 128 + c * 16));
            cpa16(so + sw, A + (size_t)(rowBase + row) * 2048 + kof + c * 8);
        }
        #pragma unroll
        for (int p = 0; p < 4; p++) {
            int chunk = tid + p * 256;
            int row = chunk >> 3, c = chunk & 7;
            uint32_t sw = swz((uint32_t)(row * 128 + c * 16));
            cpa16(so + 4096 + sw, B + (size_t)(colBase + row) * 2048 + kof + c * 8);
        }
        asm volatile("cp.async.commit_group;" ::: "memory");
    };

    load_stage(0, 0);
    load_stage(1, 1);

    for (int s = 0; s < NSTAGE; s++) {
        if (s + 2 < NSTAGE) asm volatile("cp.async.wait_group 1;" ::: "memory");
        else                asm volatile("cp.async.wait_group 0;" ::: "memory");
        __syncthreads();
        uint32_t so = sb + (uint32_t)(s & 1) * STG32;
        #pragma unroll
        for (int ks = 0; ks < 4; ks++) {
            uint32_t ah[2][4], bh[4];
            #pragma unroll
            for (int mi = 0; mi < 2; mi++) {
                int row = mi * 16 + (lane & 15);
                int ch  = ks * 2 + (lane >> 4);
                ldsm4(so + swz((uint32_t)(row * 128 + ch * 16)), ah[mi]);
            }
            {
                int row = wid * 16 + ((lane >> 4) << 3) + (lane & 7);
                int ch  = ks * 2 + ((lane >> 3) & 1);
                ldsm4(so + 4096 + swz((uint32_t)(row * 128 + ch * 16)), bh);
            }
            #pragma unroll
            for (int mi = 0; mi < 2; mi++)
                #pragma unroll
                for (int ni = 0; ni < 2; ni++)
                    mma16816(acc[mi][ni], ah[mi], &bh[ni * 2]);
        }
        __syncthreads();
        if (s + 2 < NSTAGE) load_stage(s + 2, s & 1);
    }

    #pragma unroll
    for (int mi = 0; mi < 2; mi++)
        #pragma unroll
        for (int ni = 0; ni < 2; ni++) {
            int m0  = rowBase + mi * 16 + (lane >> 2);
            int col = colBase + wid * 16 + ni * 8 + (lane & 3) * 2;
            size_t i0 = (size_t)m0 * 2048 + col;
            size_t i1 = i0 + (size_t)8 * 2048;
            float2 r0 = *(const float2*)(R + i0);
            float2 r1 = *(const float2*)(R + i1);
            *(float2*)(C + i0) = make_float2(acc[mi][ni][0] + r0.x, acc[mi][ni][1] + r0.y);
            *(float2*)(C + i1) = make_float2(acc[mi][ni][2] + r1.x, acc[mi][ni][3] + r1.y);
        }
}

extern "C" void kernel_launch(void* const* d_in, const int* in_sizes, int n_in,
                              void* d_out, int out_size) {
    const float* x  = (const float*)d_in[0];
    const float* Wq = (const float*)d_in[1];
    const float* Wk = (const float*)d_in[2];
    const float* Wv = (const float*)d_in[3];
    const float* Wo = (const float*)d_in[4];
    float* out = (float*)d_out;

    __half *xnh, *wqT, *wkT, *wvT, *woT, *oh;
    __nv_bfloat16 *kbf, *qbf;
    float *v;
    cudaGetSymbolAddress((void**)&xnh,  g_xnh);
    cudaGetSymbolAddress((void**)&wqT,  g_wqT);
    cudaGetSymbolAddress((void**)&wkT,  g_wkT);
    cudaGetSymbolAddress((void**)&wvT,  g_wvT);
    cudaGetSymbolAddress((void**)&woT,  g_woT);
    cudaGetSymbolAddress((void**)&v,    g_v);
    cudaGetSymbolAddress((void**)&kbf,  g_kbf);
    cudaGetSymbolAddress((void**)&qbf,  g_qbf);
    cudaGetSymbolAddress((void**)&oh,   g_oh);

    cudaFuncSetAttribute(proj_gemm,  cudaFuncAttributeMaxDynamicSharedMemorySize, G128_SMEM);
    cudaFuncSetAttribute(gemm32copy, cudaFuncAttributeMaxDynamicSharedMemorySize, G32_SMEM);
    cudaFuncSetAttribute(attn3,      cudaFuncAttributeMaxDynamicSharedMemorySize, ATT3_SMEM);

    // 1) LN -> fp16  +  all weight transposes (one launch)
    prep<<<2048 + 4 * 4096, 256>>>(x, xnh, Wq, Wk, Wv, Wo, wqT, wkT, wvT, woT);
    // 2) K + V + Q projections fused (K/Q with fused head-LN -> bf16)
    proj_gemm<<<544, 256, G128_SMEM>>>(xnh, wkT, wvT, wqT, kbf, v, qbf);
    // 3) sparse attention -> fp16
    attn3<<<dim3(16, 16), 256, ATT3_SMEM>>>(qbf, kbf, v, oh);
    // 4) out[0:256] = o @ Wo + x ; out[256:] = x  (one launch)
    gemm32copy<<<256, 256, G32_SMEM>>>(oh, woT, out, x, x);
}

// round 8
// speedup vs baseline: 8.8644x; 1.0377x over previous
#include <cuda_runtime.h>
#include <cuda_fp16.h>
#include <cuda_bf16.h>
#include <math.h>
#include <stdint.h>

// Problem constants
#define N_TOK 2048
#define D_MOD 2048
#define NHEAD 16
#define DHEAD 128
#define NQ    256
#define EPS   1e-5f

// ---------------- device scratch ----------------
__device__ __half         g_xnh [N_TOK * D_MOD];   // LN(x) fp16
__device__ __half         g_wqT [D_MOD * D_MOD];   // W^T fp16 (out-col major, contig k)
__device__ __half         g_wkT [D_MOD * D_MOD];
__device__ __half         g_wvT [D_MOD * D_MOD];
__device__ __half         g_woT [D_MOD * D_MOD];
__device__ __half         g_vh  [N_TOK * D_MOD];   // V projection fp16
__device__ __nv_bfloat16  g_kbf [N_TOK * D_MOD];   // head-LN(K) bf16
__device__ __nv_bfloat16  g_qbf [NQ * D_MOD];      // head-LN(Q) bf16
__device__ __half         g_oh  [NQ * D_MOD];      // attention out fp16

// ---------------- helpers ----------------
__device__ __forceinline__ uint32_t smem_u32(const void* p) {
    uint32_t a;
    asm("{ .reg .u64 t; cvta.to.shared.u64 t, %1; cvt.u32.u64 %0, t; }" : "=r"(a) : "l"(p));
    return a;
}
__device__ __forceinline__ void cpa16(uint32_t saddr, const void* gaddr) {
    asm volatile("cp.async.cg.shared.global [%0], [%1], 16;" :: "r"(saddr), "l"(gaddr));
}
__device__ __forceinline__ void ldsm4(uint32_t addr, uint32_t* r) {
    asm volatile("ldmatrix.sync.aligned.m8n8.x4.shared.b16 {%0,%1,%2,%3}, [%4];"
                 : "=r"(r[0]), "=r"(r[1]), "=r"(r[2]), "=r"(r[3]) : "r"(addr));
}
__device__ __forceinline__ void mma16816(float* c, const uint32_t* a, const uint32_t* b) {
    asm volatile("mma.sync.aligned.m16n8k16.row.col.f32.f16.f16.f32 "
        "{%0,%1,%2,%3}, {%4,%5,%6,%7}, {%8,%9}, {%0,%1,%2,%3};"
        : "+f"(c[0]), "+f"(c[1]), "+f"(c[2]), "+f"(c[3])
        : "r"(a[0]), "r"(a[1]), "r"(a[2]), "r"(a[3]), "r"(b[0]), "r"(b[1]));
}
__device__ __forceinline__ uint32_t swz(uint32_t off) {
    return off ^ ((off >> 3) & 0x70);
}

// ================ prep: LN(x)->fp16  +  4 weight transposes, one launch ==========
__global__ __launch_bounds__(256)
void prep(const float* __restrict__ x, __half* __restrict__ xh,
          const float* __restrict__ W0, const float* __restrict__ W1,
          const float* __restrict__ W2, const float* __restrict__ W3,
          __half* __restrict__ T0, __half* __restrict__ T1,
          __half* __restrict__ T2, __half* __restrict__ T3) {
    __shared__ float tile[32][33];
    __shared__ float bs[8], bss[8];
    int bid = blockIdx.x;
    int tid = threadIdx.x;

    if (bid < 2048) {
        int row = bid;
        const float4* xr = (const float4*)(x + (size_t)row * D_MOD);
        float4 a = xr[tid];
        float4 b = xr[tid + 256];
        float s  = a.x + a.y + a.z + a.w + b.x + b.y + b.z + b.w;
        float ss = a.x*a.x + a.y*a.y + a.z*a.z + a.w*a.w
                 + b.x*b.x + b.y*b.y + b.z*b.z + b.w*b.w;
        #pragma unroll
        for (int o = 16; o > 0; o >>= 1) {
            s  += __shfl_xor_sync(0xffffffffu, s,  o);
            ss += __shfl_xor_sync(0xffffffffu, ss, o);
        }
        int w = tid >> 5, l = tid & 31;
        if (l == 0) { bs[w] = s; bss[w] = ss; }
        __syncthreads();
        float ts = 0.f, tss = 0.f;
        #pragma unroll
        for (int i = 0; i < 8; i++) { ts += bs[i]; tss += bss[i]; }
        float mean = ts * (1.0f / D_MOD);
        float var  = tss * (1.0f / D_MOD) - mean * mean;
        float inv  = rsqrtf(var + EPS);
        __half2* hp = (__half2*)(xh + (size_t)row * D_MOD);
        hp[tid*2 + 0]   = __floats2half2_rn((a.x - mean) * inv, (a.y - mean) * inv);
        hp[tid*2 + 1]   = __floats2half2_rn((a.z - mean) * inv, (a.w - mean) * inv);
        hp[512 + tid*2] = __floats2half2_rn((b.x - mean) * inv, (b.y - mean) * inv);
        hp[513 + tid*2] = __floats2half2_rn((b.z - mean) * inv, (b.w - mean) * inv);
    } else {
        int t = bid - 2048;
        int which = t >> 12;
        int rem = t & 4095;
        int bx = rem & 63, by = rem >> 6;
        const float* W = (which == 0) ? W0 : (which == 1) ? W1 : (which == 2) ? W2 : W3;
        __half* T = (which == 0) ? T0 : (which == 1) ? T1 : (which == 2) ? T2 : T3;
        int tx = tid & 31, ty = tid >> 5;
        int xcol = bx * 32 + tx;
        int yrow = by * 32 + ty;
        #pragma unroll
        for (int i = 0; i < 4; i++)
            tile[ty + i*8][tx] = W[(size_t)(yrow + i*8) * D_MOD + xcol];
        __syncthreads();
        int nx = by * 32 + tx;
        int ny = bx * 32 + ty;
        #pragma unroll
        for (int i = 0; i < 4; i++)
            T[(size_t)(ny + i*8) * D_MOD + nx] = __float2half_rn(tile[tx][ty + i*8]);
    }
}

// ================ fused projections: K / V / Q in one launch ================
// modes: 0 = K (head-LN -> bf16), 1 = V (fp16), 2 = Q (head-LN -> bf16, M=256)
#define NSTAGE 32
#define STG128 32768
#define G128_SMEM (2 * STG128)

__global__ __launch_bounds__(256)
void proj_gemm(const __half* __restrict__ A,
               const __half* __restrict__ WK, const __half* __restrict__ WV,
               const __half* __restrict__ WQ,
               __nv_bfloat16* __restrict__ Kout, __half* __restrict__ Vout,
               __nv_bfloat16* __restrict__ Qout) {
    extern __shared__ __align__(1024) char smem[];
    uint32_t sb = smem_u32(smem);
    int tid = threadIdx.x, wid = tid >> 5, lane = tid & 31;
    int wr = wid >> 2, wc = wid & 3;

    int bid = blockIdx.x, mode, tx, ty;
    const __half* B;
    if (bid < 256)      { mode = 0; tx = bid & 15; ty = bid >> 4; B = WK; }
    else if (bid < 512) { mode = 1; tx = (bid - 256) & 15; ty = (bid - 256) >> 4; B = WV; }
    else                { mode = 2; tx = (bid - 512) & 15; ty = (bid - 512) >> 4; B = WQ; }
    int rowBase = ty * 128, colBase = tx * 128;

    float acc[4][4][4];
    #pragma unroll
    for (int mi = 0; mi < 4; mi++)
        #pragma unroll
        for (int ni = 0; ni < 4; ni++)
            #pragma unroll
            for (int r = 0; r < 4; r++) acc[mi][ni][r] = 0.f;

    auto load_stage = [&](int s, int buf) {
        uint32_t so = sb + (uint32_t)buf * STG128;
        size_t kof = (size_t)s * 64;
        #pragma unroll
        for (int p = 0; p < 4; p++) {
            int chunk = tid + p * 256;
            int row = chunk >> 3, c = chunk & 7;
            uint32_t sw = swz((uint32_t)(row * 128 + c * 16));
            cpa16(so + sw,         A + (size_t)(rowBase + row) * 2048 + kof + c * 8);
            cpa16(so + 16384 + sw, B + (size_t)(colBase + row) * 2048 + kof + c * 8);
        }
        asm volatile("cp.async.commit_group;" ::: "memory");
    };

    load_stage(0, 0);
    load_stage(1, 1);

    for (int s = 0; s < NSTAGE; s++) {
        if (s + 2 < NSTAGE) asm volatile("cp.async.wait_group 1;" ::: "memory");
        else                asm volatile("cp.async.wait_group 0;" ::: "memory");
        __syncthreads();
        uint32_t so = sb + (uint32_t)(s & 1) * STG128;
        #pragma unroll
        for (int ks = 0; ks < 4; ks++) {
            uint32_t ah[4][4], bh[2][4];
            #pragma unroll
            for (int mi = 0; mi < 4; mi++) {
                int row = wr * 64 + mi * 16 + (lane & 15);
                int ch  = ks * 2 + (lane >> 4);
                ldsm4(so + swz((uint32_t)(row * 128 + ch * 16)), ah[mi]);
            }
            #pragma unroll
            for (int p = 0; p < 2; p++) {
                int row = wc * 32 + p * 16 + ((lane >> 4) << 3) + (lane & 7);
                int ch  = ks * 2 + ((lane >> 3) & 1);
                ldsm4(so + 16384 + swz((uint32_t)(row * 128 + ch * 16)), bh[p]);
            }
            #pragma unroll
            for (int mi = 0; mi < 4; mi++)
                #pragma unroll
                for (int ni = 0; ni < 4; ni++)
                    mma16816(acc[mi][ni], ah[mi], &bh[ni >> 1][(ni & 1) * 2]);
        }
        __syncthreads();
        if (s + 2 < NSTAGE) load_stage(s + 2, s & 1);
    }

    if (mode == 1) {
        // V: fp16 store
        #pragma unroll
        for (int mi = 0; mi < 4; mi++)
            #pragma unroll
            for (int ni = 0; ni < 4; ni++) {
                int m0  = rowBase + wr * 64 + mi * 16 + (lane >> 2);
                int col = colBase + wc * 32 + ni * 8 + (lane & 3) * 2;
                size_t i0 = (size_t)m0 * 2048 + col;
                size_t i1 = i0 + (size_t)8 * 2048;
                *(__half2*)(Vout + i0) = __floats2half2_rn(acc[mi][ni][0], acc[mi][ni][1]);
                *(__half2*)(Vout + i1) = __floats2half2_rn(acc[mi][ni][2], acc[mi][ni][3]);
            }
        return;
    }

    // K / Q: fused per-head LayerNorm over the 128 cols of this tile, -> bf16
    __nv_bfloat16* Out = (mode == 0) ? Kout : Qout;
    float sv[4][2], qv[4][2];
    #pragma unroll
    for (int mi = 0; mi < 4; mi++)
        #pragma unroll
        for (int h = 0; h < 2; h++) {
            float s = 0.f, q = 0.f;
            #pragma unroll
            for (int ni = 0; ni < 4; ni++) {
                float a0 = acc[mi][ni][h*2 + 0], a1 = acc[mi][ni][h*2 + 1];
                s += a0 + a1;
                q += a0*a0 + a1*a1;
            }
            s += __shfl_xor_sync(0xffffffffu, s, 1);
            s += __shfl_xor_sync(0xffffffffu, s, 2);
            q += __shfl_xor_sync(0xffffffffu, q, 1);
            q += __shfl_xor_sync(0xffffffffu, q, 2);
            sv[mi][h] = s;
            qv[mi][h] = q;
        }
    __syncthreads();
    float* sArr = (float*)smem;
    float* qArr = ((float*)smem) + 512;
    if ((lane & 3) == 0) {
        #pragma unroll
        for (int mi = 0; mi < 4; mi++)
            #pragma unroll
            for (int h = 0; h < 2; h++) {
                int row = wr * 64 + mi * 16 + (lane >> 2) + h * 8;
                sArr[wc * 128 + row] = sv[mi][h];
                qArr[wc * 128 + row] = qv[mi][h];
            }
    }
    __syncthreads();
    #pragma unroll
    for (int mi = 0; mi < 4; mi++)
        #pragma unroll
        for (int h = 0; h < 2; h++) {
            int row = wr * 64 + mi * 16 + (lane >> 2) + h * 8;
            float S = sArr[row] + sArr[128 + row] + sArr[256 + row] + sArr[384 + row];
            float Q = qArr[row] + qArr[128 + row] + qArr[256 + row] + qArr[384 + row];
            float mean = S * (1.0f / 128.0f);
            float var  = Q * (1.0f / 128.0f) - mean * mean;
            float inv  = rsqrtf(var + EPS);
            int m = rowBase + row;
            #pragma unroll
            for (int ni = 0; ni < 4; ni++) {
                int col = colBase + wc * 32 + ni * 8 + (lane & 3) * 2;
                float a0 = (acc[mi][ni][h*2 + 0] - mean) * inv;
                float a1 = (acc[mi][ni][h*2 + 1] - mean) * inv;
                *(__nv_bfloat162*)(Out + (size_t)m * 2048 + col) = __floats2bfloat162_rn(a0, a1);
            }
        }
}

// ================ sparse attention v3: block=(b,h), 256 threads ================
// smem: qs[16][128] f32 | ps[16][128] f32 | vs[128][128] f32 | ks[128][132] bf16
#define KROWB 264
#define ATT3_SMEM (8192 + 8192 + 65536 + 128 * KROWB)

__global__ __launch_bounds__(256)
void attn3(const __nv_bfloat16* __restrict__ qbf, const __nv_bfloat16* __restrict__ kbf,
           const __half* __restrict__ v, __half* __restrict__ o) {
    extern __shared__ __align__(16) char asmem[];
    float* qs = (float*)asmem;                     // [16][128]
    float* ps = qs + 2048;                         // [16][128]
    float* vs = ps + 2048;                         // [128][128]
    char*  ks = asmem + 8192 + 8192 + 65536;       // [128][264B]
    __shared__ float redm[16][4], reds[16][4];
    int b = blockIdx.x, h = blockIdx.y;
    int tid = threadIdx.x, lane = tid & 31;
    int w4 = (tid >> 5) & 3;

    // ---- Q ----
    {
        int r = tid >> 4, c = tid & 15;
        uint4 qv = *(const uint4*)(qbf + (size_t)(16*b + r) * D_MOD + h * DHEAD + c * 8);
        const __nv_bfloat162* qb = (const __nv_bfloat162*)&qv;
        float2 f0 = __bfloat1622float2(qb[0]);
        float2 f1 = __bfloat1622float2(qb[1]);
        float2 f2 = __bfloat1622float2(qb[2]);
        float2 f3 = __bfloat1622float2(qb[3]);
        *(float4*)(qs + r * 128 + c * 8)     = make_float4(f0.x, f0.y, f1.x, f1.y);
        *(float4*)(qs + r * 128 + c * 8 + 4) = make_float4(f2.x, f2.y, f3.x, f3.y);
    }
    // ---- K: 16 independent 8B loads ----
    #pragma unroll
    for (int p = 0; p < 16; p++) {
        int idx = tid + p * 256;
        int j = idx >> 5, c = idx & 31;
        uint2 kk = *(const uint2*)(kbf + (size_t)(b + 16*j) * D_MOD + h * DHEAD + c * 4);
        *(uint2*)(ks + j * KROWB + c * 8) = kk;
    }
    // ---- V: fp16 gmem -> fp32 smem, 16 independent 8B loads ----
    #pragma unroll
    for (int p = 0; p < 16; p++) {
        int idx = tid + p * 256;
        int j = idx >> 5, c = idx & 31;
        uint2 vv = *(const uint2*)(v + (size_t)(b + 16*j) * D_MOD + h * DHEAD + c * 4);
        float2 v01 = __half22float2(*(const __half2*)&vv.x);
        float2 v23 = __half22float2(*(const __half2*)&vv.y);
        *(float4*)(vs + j * 128 + c * 4) = make_float4(v01.x, v01.y, v23.x, v23.y);
    }
    __syncthreads();

    // ---- scores: thread = (j, rhalf); 8 rows each ----
    int j = tid & 127, rh = tid >> 7;
    float s[8];
    #pragma unroll
    for (int r8 = 0; r8 < 8; r8++) s[r8] = 0.f;
    #pragma unroll 4
    for (int d4 = 0; d4 < 32; d4++) {
        uint2 kk = *(const uint2*)(ks + j * KROWB + d4 * 8);
        float2 k01 = __bfloat1622float2(*(const __nv_bfloat162*)&kk.x);
        float2 k23 = __bfloat1622float2(*(const __nv_bfloat162*)&kk.y);
        #pragma unroll
        for (int r8 = 0; r8 < 8; r8++) {
            float4 qv = *(const float4*)(qs + (rh * 8 + r8) * 128 + d4 * 4);
            s[r8] += qv.x * k01.x + qv.y * k01.y + qv.z * k23.x + qv.w * k23.y;
        }
    }
    const float SC = 0.08838834764831845f;
    #pragma unroll
    for (int r8 = 0; r8 < 8; r8++) s[r8] *= SC;

    // ---- softmax ----
    #pragma unroll
    for (int r8 = 0; r8 < 8; r8++) {
        float m = s[r8];
        #pragma unroll
        for (int off = 16; off > 0; off >>= 1) m = fmaxf(m, __shfl_xor_sync(0xffffffffu, m, off));
        if (lane == 0) redm[rh * 8 + r8][w4] = m;
    }
    __syncthreads();
    #pragma unroll
    for (int r8 = 0; r8 < 8; r8++) {
        int r = rh * 8 + r8;
        float mx = fmaxf(fmaxf(redm[r][0], redm[r][1]), fmaxf(redm[r][2], redm[r][3]));
        float p = __expf(s[r8] - mx);
        ps[r * 128 + j] = p;
        float t = p;
        #pragma unroll
        for (int off = 16; off > 0; off >>= 1) t += __shfl_xor_sync(0xffffffffu, t, off);
        if (lane == 0) reds[r][w4] = t;
    }
    __syncthreads();
    float invr[8];
    #pragma unroll
    for (int r8 = 0; r8 < 8; r8++) {
        int r = rh * 8 + r8;
        invr[r8] = 1.0f / fmaxf(reds[r][0] + reds[r][1] + reds[r][2] + reds[r][3], 1e-30f);
    }

    // ---- output ----
    int d = tid & 127;
    float acc[8];
    #pragma unroll
    for (int r8 = 0; r8 < 8; r8++) acc[r8] = 0.f;
    #pragma unroll 4
    for (int jj = 0; jj < 128; jj++) {
        float vv = vs[jj * 128 + d];
        #pragma unroll
        for (int r8 = 0; r8 < 8; r8++)
            acc[r8] += ps[(rh * 8 + r8) * 128 + jj] * vv;
    }
    #pragma unroll
    for (int r8 = 0; r8 < 8; r8++) {
        int r = rh * 8 + r8;
        o[(size_t)(16*b + r) * D_MOD + h * DHEAD + d] = __float2half_rn(acc[r8] * invr[r8]);
    }
}

// ================ Wo GEMM (M=256) 4-stage + tail residual copy, one launch ======
#define STG32 20480
#define G32_SMEM (4 * STG32)

__global__ __launch_bounds__(256)
void gemm32copy(const __half* __restrict__ A, const __half* __restrict__ B,
                float* __restrict__ C, const float* __restrict__ R,
                const float* __restrict__ x) {
    int bid = blockIdx.x;
    int tid = threadIdx.x;

    if (bid >= 128) {
        const size_t count = (size_t)(N_TOK - NQ) * D_MOD / 4;
        const float4* xs = (const float4*)(x + (size_t)NQ * D_MOD);
        float4* od = (float4*)(C + (size_t)NQ * D_MOD);
        for (size_t i = (size_t)(bid - 128) * 256 + tid; i < count; i += 128 * 256)
            od[i] = xs[i];
        return;
    }

    extern __shared__ __align__(1024) char smem[];
    uint32_t sb = smem_u32(smem);
    int wid = tid >> 5, lane = tid & 31;
    int rowBase = (bid >> 4) * 32, colBase = (bid & 15) * 128;

    float acc[2][2][4];
    #pragma unroll
    for (int mi = 0; mi < 2; mi++)
        #pragma unroll
        for (int ni = 0; ni < 2; ni++)
            #pragma unroll
            for (int r = 0; r < 4; r++) acc[mi][ni][r] = 0.f;

    auto load_stage = [&](int s) {
        uint32_t so = sb + (uint32_t)(s & 3) * STG32;
        size_t kof = (size_t)s * 64;
        {
            int row = tid >> 3, c = tid & 7;
            uint32_t sw = swz((uint32_t)(row * 128 + c * 16));
            cpa16(so + sw, A + (size_t)(rowBase + row) * 2048 + kof + c * 8);
        }
        #pragma unroll
        for (int p = 0; p < 4; p++) {
            int chunk = tid + p * 256;
            int row = chunk >> 3, c = chunk & 7;
            uint32_t sw = swz((uint32_t)(row * 128 + c * 16));
            cpa16(so + 4096 + sw, B + (size_t)(colBase + row) * 2048 + kof + c * 8);
        }
        asm volatile("cp.async.commit_group;" ::: "memory");
    };

    load_stage(0);
    load_stage(1);
    load_stage(2);

    for (int s = 0; s < NSTAGE; s++) {
        if (s + 3 < NSTAGE) asm volatile("cp.async.wait_group 2;" ::: "memory");
        else                asm volatile("cp.async.wait_group 0;" ::: "memory");
        __syncthreads();
        uint32_t so = sb + (uint32_t)(s & 3) * STG32;
        #pragma unroll
        for (int ks = 0; ks < 4; ks++) {
            uint32_t ah[2][4], bh[4];
            #pragma unroll
            for (int mi = 0; mi < 2; mi++) {
                int row = mi * 16 + (lane & 15);
                int ch  = ks * 2 + (lane >> 4);
                ldsm4(so + swz((uint32_t)(row * 128 + ch * 16)), ah[mi]);
            }
            {
                int row = wid * 16 + ((lane >> 4) << 3) + (lane & 7);
                int ch  = ks * 2 + ((lane >> 3) & 1);
                ldsm4(so + 4096 + swz((uint32_t)(row * 128 + ch * 16)), bh);
            }
            #pragma unroll
            for (int mi = 0; mi < 2; mi++)
                #pragma unroll
                for (int ni = 0; ni < 2; ni++)
                    mma16816(acc[mi][ni], ah[mi], &bh[ni * 2]);
        }
        __syncthreads();
        if (s + 3 < NSTAGE) load_stage(s + 3);
    }

    #pragma unroll
    for (int mi = 0; mi < 2; mi++)
        #pragma unroll
        for (int ni = 0; ni < 2; ni++) {
            int m0  = rowBase + mi * 16 + (lane >> 2);
            int col = colBase + wid * 16 + ni * 8 + (lane & 3) * 2;
            size_t i0 = (size_t)m0 * 2048 + col;
            size_t i1 = i0 + (size_t)8 * 2048;
            float2 r0 = *(const float2*)(R + i0);
            float2 r1 = *(const float2*)(R + i1);
            *(float2*)(C + i0) = make_float2(acc[mi][ni][0] + r0.x, acc[mi][ni][1] + r0.y);
            *(float2*)(C + i1) = make_float2(acc[mi][ni][2] + r1.x, acc[mi][ni][3] + r1.y);
        }
}

extern "C" void kernel_launch(void* const* d_in, const int* in_sizes, int n_in,
                              void* d_out, int out_size) {
    const float* x  = (const float*)d_in[0];
    const float* Wq = (const float*)d_in[1];
    const float* Wk = (const float*)d_in[2];
    const float* Wv = (const float*)d_in[3];
    const float* Wo = (const float*)d_in[4];
    float* out = (float*)d_out;

    __half *xnh, *wqT, *wkT, *wvT, *woT, *oh, *vh;
    __nv_bfloat16 *kbf, *qbf;
    cudaGetSymbolAddress((void**)&xnh,  g_xnh);
    cudaGetSymbolAddress((void**)&wqT,  g_wqT);
    cudaGetSymbolAddress((void**)&wkT,  g_wkT);
    cudaGetSymbolAddress((void**)&wvT,  g_wvT);
    cudaGetSymbolAddress((void**)&woT,  g_woT);
    cudaGetSymbolAddress((void**)&vh,   g_vh);
    cudaGetSymbolAddress((void**)&kbf,  g_kbf);
    cudaGetSymbolAddress((void**)&qbf,  g_qbf);
    cudaGetSymbolAddress((void**)&oh,   g_oh);

    cudaFuncSetAttribute(proj_gemm,  cudaFuncAttributeMaxDynamicSharedMemorySize, G128_SMEM);
    cudaFuncSetAttribute(gemm32copy, cudaFuncAttributeMaxDynamicSharedMemorySize, G32_SMEM);
    cudaFuncSetAttribute(attn3,      cudaFuncAttributeMaxDynamicSharedMemorySize, ATT3_SMEM);

    // 1) LN -> fp16  +  all weight transposes (one launch)
    prep<<<2048 + 4 * 4096, 256>>>(x, xnh, Wq, Wk, Wv, Wo, wqT, wkT, wvT, woT);
    // 2) K + V + Q projections fused (K/Q with fused head-LN -> bf16; V fp16)
    proj_gemm<<<544, 256, G128_SMEM>>>(xnh, wkT, wvT, wqT, kbf, vh, qbf);
    // 3) sparse attention -> fp16
    attn3<<<dim3(16, 16), 256, ATT3_SMEM>>>(qbf, kbf, vh, oh);
    // 4) out[0:256] = o @ Wo + x ; out[256:] = x  (one launch)
    gemm32copy<<<256, 256, G32_SMEM>>>(oh, woT, out, x, x);
}

// round 9
// speedup vs baseline: 9.2739x; 1.0462x over previous
#include <cuda_runtime.h>
#include <cuda_fp16.h>
#include <cuda_bf16.h>
#include <math.h>
#include <stdint.h>

// Problem constants
#define N_TOK 2048
#define D_MOD 2048
#define NHEAD 16
#define DHEAD 128
#define NQ    256
#define EPS   1e-5f

// ---------------- device scratch ----------------
__device__ __half         g_xnh [N_TOK * D_MOD];   // LN(x) fp16
__device__ __half         g_wqT [D_MOD * D_MOD];   // W^T fp16 (out-col major, contig k)
__device__ __half         g_wkT [D_MOD * D_MOD];
__device__ __half         g_wvT [D_MOD * D_MOD];
__device__ __half         g_woT [D_MOD * D_MOD];
__device__ __half         g_vh  [N_TOK * D_MOD];   // V projection fp16
__device__ __nv_bfloat16  g_kbf [N_TOK * D_MOD];   // head-LN(K) bf16
__device__ __nv_bfloat16  g_qbf [NQ * D_MOD];      // head-LN(Q) bf16
__device__ __half         g_oh  [NQ * D_MOD];      // attention out fp16

// ---------------- helpers ----------------
__device__ __forceinline__ uint32_t smem_u32(const void* p) {
    uint32_t a;
    asm("{ .reg .u64 t; cvta.to.shared.u64 t, %1; cvt.u32.u64 %0, t; }" : "=r"(a) : "l"(p));
    return a;
}
__device__ __forceinline__ void cpa16(uint32_t saddr, const void* gaddr) {
    asm volatile("cp.async.cg.shared.global [%0], [%1], 16;" :: "r"(saddr), "l"(gaddr));
}
__device__ __forceinline__ void ldsm4(uint32_t addr, uint32_t* r) {
    asm volatile("ldmatrix.sync.aligned.m8n8.x4.shared.b16 {%0,%1,%2,%3}, [%4];"
                 : "=r"(r[0]), "=r"(r[1]), "=r"(r[2]), "=r"(r[3]) : "r"(addr));
}
__device__ __forceinline__ void mma16816(float* c, const uint32_t* a, const uint32_t* b) {
    asm volatile("mma.sync.aligned.m16n8k16.row.col.f32.f16.f16.f32 "
        "{%0,%1,%2,%3}, {%4,%5,%6,%7}, {%8,%9}, {%0,%1,%2,%3};"
        : "+f"(c[0]), "+f"(c[1]), "+f"(c[2]), "+f"(c[3])
        : "r"(a[0]), "r"(a[1]), "r"(a[2]), "r"(a[3]), "r"(b[0]), "r"(b[1]));
}
__device__ __forceinline__ uint32_t swz(uint32_t off) {
    return off ^ ((off >> 3) & 0x70);
}

// ================ prep: LN(x)->fp16  +  4 weight transposes (64x64 tiles) =========
// blocks [0, 2048): LayerNorm rows
// blocks [2048, 2048 + 4*1024): 64x64 transpose tiles (which = (bid-2048)>>10)
__global__ __launch_bounds__(256)
void prep(const float* __restrict__ x, __half* __restrict__ xh,
          const float* __restrict__ W0, const float* __restrict__ W1,
          const float* __restrict__ W2, const float* __restrict__ W3,
          __half* __restrict__ T0, __half* __restrict__ T1,
          __half* __restrict__ T2, __half* __restrict__ T3) {
    __shared__ float tile[64][65];
    __shared__ float bs[8], bss[8];
    int bid = blockIdx.x;
    int tid = threadIdx.x;

    if (bid < 2048) {
        int row = bid;
        const float4* xr = (const float4*)(x + (size_t)row * D_MOD);
        float4 a = xr[tid];
        float4 b = xr[tid + 256];
        float s  = a.x + a.y + a.z + a.w + b.x + b.y + b.z + b.w;
        float ss = a.x*a.x + a.y*a.y + a.z*a.z + a.w*a.w
                 + b.x*b.x + b.y*b.y + b.z*b.z + b.w*b.w;
        #pragma unroll
        for (int o = 16; o > 0; o >>= 1) {
            s  += __shfl_xor_sync(0xffffffffu, s,  o);
            ss += __shfl_xor_sync(0xffffffffu, ss, o);
        }
        int w = tid >> 5, l = tid & 31;
        if (l == 0) { bs[w] = s; bss[w] = ss; }
        __syncthreads();
        float ts = 0.f, tss = 0.f;
        #pragma unroll
        for (int i = 0; i < 8; i++) { ts += bs[i]; tss += bss[i]; }
        float mean = ts * (1.0f / D_MOD);
        float var  = tss * (1.0f / D_MOD) - mean * mean;
        float inv  = rsqrtf(var + EPS);
        __half2* hp = (__half2*)(xh + (size_t)row * D_MOD);
        hp[tid*2 + 0]   = __floats2half2_rn((a.x - mean) * inv, (a.y - mean) * inv);
        hp[tid*2 + 1]   = __floats2half2_rn((a.z - mean) * inv, (a.w - mean) * inv);
        hp[512 + tid*2] = __floats2half2_rn((b.x - mean) * inv, (b.y - mean) * inv);
        hp[513 + tid*2] = __floats2half2_rn((b.z - mean) * inv, (b.w - mean) * inv);
    } else {
        // ---- 64x64 transpose tile with fp16 16B vector stores ----
        int t = bid - 2048;
        int which = t >> 10;
        int rem = t & 1023;
        int bx = rem & 31, by = rem >> 5;   // bx: n-tile, by: k-tile
        const float* W = (which == 0) ? W0 : (which == 1) ? W1 : (which == 2) ? W2 : W3;
        __half* T = (which == 0) ? T0 : (which == 1) ? T1 : (which == 2) ? T2 : T3;
        int rr = tid >> 4, c4 = tid & 15;
        #pragma unroll
        for (int p = 0; p < 4; p++) {
            int r = rr + p * 16;   // k within tile
            float4 v = *(const float4*)(W + (size_t)(by*64 + r) * D_MOD + bx*64 + c4*4);
            tile[r][c4*4 + 0] = v.x;
            tile[r][c4*4 + 1] = v.y;
            tile[r][c4*4 + 2] = v.z;
            tile[r][c4*4 + 3] = v.w;
        }
        __syncthreads();
        #pragma unroll
        for (int p = 0; p < 2; p++) {
            int idx = tid + p * 256;       // 0..511
            int nl = idx >> 3, c8 = idx & 7;
            __half2 h0 = __floats2half2_rn(tile[c8*8 + 0][nl], tile[c8*8 + 1][nl]);
            __half2 h1 = __floats2half2_rn(tile[c8*8 + 2][nl], tile[c8*8 + 3][nl]);
            __half2 h2 = __floats2half2_rn(tile[c8*8 + 4][nl], tile[c8*8 + 5][nl]);
            __half2 h3 = __floats2half2_rn(tile[c8*8 + 6][nl], tile[c8*8 + 7][nl]);
            uint4 pk;
            pk.x = *(uint32_t*)&h0; pk.y = *(uint32_t*)&h1;
            pk.z = *(uint32_t*)&h2; pk.w = *(uint32_t*)&h3;
            *(uint4*)(T + (size_t)(bx*64 + nl) * D_MOD + by*64 + c8*8) = pk;
        }
    }
}

// ================ fused projections: Q / K / V in one launch ================
// bid <  32 : Q (head-LN -> bf16, M=256)    [scheduled first: shortest]
// bid < 288 : K (head-LN -> bf16)
// else      : V (fp16)
#define NSTAGE 32
#define STG128 32768
#define G128_SMEM (2 * STG128)

__global__ __launch_bounds__(256)
void proj_gemm(const __half* __restrict__ A,
               const __half* __restrict__ WK, const __half* __restrict__ WV,
               const __half* __restrict__ WQ,
               __nv_bfloat16* __restrict__ Kout, __half* __restrict__ Vout,
               __nv_bfloat16* __restrict__ Qout) {
    extern __shared__ __align__(1024) char smem[];
    uint32_t sb = smem_u32(smem);
    int tid = threadIdx.x, wid = tid >> 5, lane = tid & 31;
    int wr = wid >> 2, wc = wid & 3;

    int bid = blockIdx.x, mode, tx, ty;
    const __half* B;
    if (bid < 32)       { mode = 2; tx = bid & 15; ty = bid >> 4; B = WQ; }
    else if (bid < 288) { mode = 0; tx = (bid - 32) & 15; ty = (bid - 32) >> 4; B = WK; }
    else                { mode = 1; tx = (bid - 288) & 15; ty = (bid - 288) >> 4; B = WV; }
    int rowBase = ty * 128, colBase = tx * 128;

    float acc[4][4][4];
    #pragma unroll
    for (int mi = 0; mi < 4; mi++)
        #pragma unroll
        for (int ni = 0; ni < 4; ni++)
            #pragma unroll
            for (int r = 0; r < 4; r++) acc[mi][ni][r] = 0.f;

    auto load_stage = [&](int s, int buf) {
        uint32_t so = sb + (uint32_t)buf * STG128;
        size_t kof = (size_t)s * 64;
        #pragma unroll
        for (int p = 0; p < 4; p++) {
            int chunk = tid + p * 256;
            int row = chunk >> 3, c = chunk & 7;
            uint32_t sw = swz((uint32_t)(row * 128 + c * 16));
            cpa16(so + sw,         A + (size_t)(rowBase + row) * 2048 + kof + c * 8);
            cpa16(so + 16384 + sw, B + (size_t)(colBase + row) * 2048 + kof + c * 8);
        }
        asm volatile("cp.async.commit_group;" ::: "memory");
    };

    load_stage(0, 0);
    load_stage(1, 1);

    for (int s = 0; s < NSTAGE; s++) {
        if (s + 2 < NSTAGE) asm volatile("cp.async.wait_group 1;" ::: "memory");
        else                asm volatile("cp.async.wait_group 0;" ::: "memory");
        __syncthreads();
        uint32_t so = sb + (uint32_t)(s & 1) * STG128;
        #pragma unroll
        for (int ks = 0; ks < 4; ks++) {
            uint32_t ah[4][4], bh[2][4];
            #pragma unroll
            for (int mi = 0; mi < 4; mi++) {
                int row = wr * 64 + mi * 16 + (lane & 15);
                int ch  = ks * 2 + (lane >> 4);
                ldsm4(so + swz((uint32_t)(row * 128 + ch * 16)), ah[mi]);
            }
            #pragma unroll
            for (int p = 0; p < 2; p++) {
                int row = wc * 32 + p * 16 + ((lane >> 4) << 3) + (lane & 7);
                int ch  = ks * 2 + ((lane >> 3) & 1);
                ldsm4(so + 16384 + swz((uint32_t)(row * 128 + ch * 16)), bh[p]);
            }
            #pragma unroll
            for (int mi = 0; mi < 4; mi++)
                #pragma unroll
                for (int ni = 0; ni < 4; ni++)
                    mma16816(acc[mi][ni], ah[mi], &bh[ni >> 1][(ni & 1) * 2]);
        }
        __syncthreads();
        if (s + 2 < NSTAGE) load_stage(s + 2, s & 1);
    }

    if (mode == 1) {
        #pragma unroll
        for (int mi = 0; mi < 4; mi++)
            #pragma unroll
            for (int ni = 0; ni < 4; ni++) {
                int m0  = rowBase + wr * 64 + mi * 16 + (lane >> 2);
                int col = colBase + wc * 32 + ni * 8 + (lane & 3) * 2;
                size_t i0 = (size_t)m0 * 2048 + col;
                size_t i1 = i0 + (size_t)8 * 2048;
                *(__half2*)(Vout + i0) = __floats2half2_rn(acc[mi][ni][0], acc[mi][ni][1]);
                *(__half2*)(Vout + i1) = __floats2half2_rn(acc[mi][ni][2], acc[mi][ni][3]);
            }
        return;
    }

    // K / Q: fused per-head LayerNorm over the 128 cols of this tile, -> bf16
    __nv_bfloat16* Out = (mode == 0) ? Kout : Qout;
    float sv[4][2], qv[4][2];
    #pragma unroll
    for (int mi = 0; mi < 4; mi++)
        #pragma unroll
        for (int h = 0; h < 2; h++) {
            float s = 0.f, q = 0.f;
            #pragma unroll
            for (int ni = 0; ni < 4; ni++) {
                float a0 = acc[mi][ni][h*2 + 0], a1 = acc[mi][ni][h*2 + 1];
                s += a0 + a1;
                q += a0*a0 + a1*a1;
            }
            s += __shfl_xor_sync(0xffffffffu, s, 1);
            s += __shfl_xor_sync(0xffffffffu, s, 2);
            q += __shfl_xor_sync(0xffffffffu, q, 1);
            q += __shfl_xor_sync(0xffffffffu, q, 2);
            sv[mi][h] = s;
            qv[mi][h] = q;
        }
    __syncthreads();
    float* sArr = (float*)smem;
    float* qArr = ((float*)smem) + 512;
    if ((lane & 3) == 0) {
        #pragma unroll
        for (int mi = 0; mi < 4; mi++)
            #pragma unroll
            for (int h = 0; h < 2; h++) {
                int row = wr * 64 + mi * 16 + (lane >> 2) + h * 8;
                sArr[wc * 128 + row] = sv[mi][h];
                qArr[wc * 128 + row] = qv[mi][h];
            }
    }
    __syncthreads();
    #pragma unroll
    for (int mi = 0; mi < 4; mi++)
        #pragma unroll
        for (int h = 0; h < 2; h++) {
            int row = wr * 64 + mi * 16 + (lane >> 2) + h * 8;
            float S = sArr[row] + sArr[128 + row] + sArr[256 + row] + sArr[384 + row];
            float Q = qArr[row] + qArr[128 + row] + qArr[256 + row] + qArr[384 + row];
            float mean = S * (1.0f / 128.0f);
            float var  = Q * (1.0f / 128.0f) - mean * mean;
            float inv  = rsqrtf(var + EPS);
            int m = rowBase + row;
            #pragma unroll
            for (int ni = 0; ni < 4; ni++) {
                int col = colBase + wc * 32 + ni * 8 + (lane & 3) * 2;
                float a0 = (acc[mi][ni][h*2 + 0] - mean) * inv;
                float a1 = (acc[mi][ni][h*2 + 1] - mean) * inv;
                *(__nv_bfloat162*)(Out + (size_t)m * 2048 + col) = __floats2bfloat162_rn(a0, a1);
            }
        }
}

// ================ sparse attention v3: block=(b,h), 256 threads ================
#define KROWB 264
#define ATT3_SMEM (8192 + 8192 + 65536 + 128 * KROWB)

__global__ __launch_bounds__(256)
void attn3(const __nv_bfloat16* __restrict__ qbf, const __nv_bfloat16* __restrict__ kbf,
           const __half* __restrict__ v, __half* __restrict__ o) {
    extern __shared__ __align__(16) char asmem[];
    float* qs = (float*)asmem;                     // [16][128]
    float* ps = qs + 2048;                         // [16][128]
    float* vs = ps + 2048;                         // [128][128]
    char*  ks = asmem + 8192 + 8192 + 65536;       // [128][264B]
    __shared__ float redm[16][4], reds[16][4];
    int b = blockIdx.x, h = blockIdx.y;
    int tid = threadIdx.x, lane = tid & 31;
    int w4 = (tid >> 5) & 3;

    {
        int r = tid >> 4, c = tid & 15;
        uint4 qv = *(const uint4*)(qbf + (size_t)(16*b + r) * D_MOD + h * DHEAD + c * 8);
        const __nv_bfloat162* qb = (const __nv_bfloat162*)&qv;
        float2 f0 = __bfloat1622float2(qb[0]);
        float2 f1 = __bfloat1622float2(qb[1]);
        float2 f2 = __bfloat1622float2(qb[2]);
        float2 f3 = __bfloat1622float2(qb[3]);
        *(float4*)(qs + r * 128 + c * 8)     = make_float4(f0.x, f0.y, f1.x, f1.y);
        *(float4*)(qs + r * 128 + c * 8 + 4) = make_float4(f2.x, f2.y, f3.x, f3.y);
    }
    #pragma unroll
    for (int p = 0; p < 16; p++) {
        int idx = tid + p * 256;
        int j = idx >> 5, c = idx & 31;
        uint2 kk = *(const uint2*)(kbf + (size_t)(b + 16*j) * D_MOD + h * DHEAD + c * 4);
        *(uint2*)(ks + j * KROWB + c * 8) = kk;
    }
    #pragma unroll
    for (int p = 0; p < 16; p++) {
        int idx = tid + p * 256;
        int j = idx >> 5, c = idx & 31;
        uint2 vv = *(const uint2*)(v + (size_t)(b + 16*j) * D_MOD + h * DHEAD + c * 4);
        float2 v01 = __half22float2(*(const __half2*)&vv.x);
        float2 v23 = __half22float2(*(const __half2*)&vv.y);
        *(float4*)(vs + j * 128 + c * 4) = make_float4(v01.x, v01.y, v23.x, v23.y);
    }
    __syncthreads();

    int j = tid & 127, rh = tid >> 7;
    float s[8];
    #pragma unroll
    for (int r8 = 0; r8 < 8; r8++) s[r8] = 0.f;
    #pragma unroll 4
    for (int d4 = 0; d4 < 32; d4++) {
        uint2 kk = *(const uint2*)(ks + j * KROWB + d4 * 8);
        float2 k01 = __bfloat1622float2(*(const __nv_bfloat162*)&kk.x);
        float2 k23 = __bfloat1622float2(*(const __nv_bfloat162*)&kk.y);
        #pragma unroll
        for (int r8 = 0; r8 < 8; r8++) {
            float4 qv = *(const float4*)(qs + (rh * 8 + r8) * 128 + d4 * 4);
            s[r8] += qv.x * k01.x + qv.y * k01.y + qv.z * k23.x + qv.w * k23.y;
        }
    }
    const float SC = 0.08838834764831845f;
    #pragma unroll
    for (int r8 = 0; r8 < 8; r8++) s[r8] *= SC;

    #pragma unroll
    for (int r8 = 0; r8 < 8; r8++) {
        float m = s[r8];
        #pragma unroll
        for (int off = 16; off > 0; off >>= 1) m = fmaxf(m, __shfl_xor_sync(0xffffffffu, m, off));
        if (lane == 0) redm[rh * 8 + r8][w4] = m;
    }
    __syncthreads();
    #pragma unroll
    for (int r8 = 0; r8 < 8; r8++) {
        int r = rh * 8 + r8;
        float mx = fmaxf(fmaxf(redm[r][0], redm[r][1]), fmaxf(redm[r][2], redm[r][3]));
        float p = __expf(s[r8] - mx);
        ps[r * 128 + j] = p;
        float t = p;
        #pragma unroll
        for (int off = 16; off > 0; off >>= 1) t += __shfl_xor_sync(0xffffffffu, t, off);
        if (lane == 0) reds[r][w4] = t;
    }
    __syncthreads();
    float invr[8];
    #pragma unroll
    for (int r8 = 0; r8 < 8; r8++) {
        int r = rh * 8 + r8;
        invr[r8] = 1.0f / fmaxf(reds[r][0] + reds[r][1] + reds[r][2] + reds[r][3], 1e-30f);
    }

    int d = tid & 127;
    float acc[8];
    #pragma unroll
    for (int r8 = 0; r8 < 8; r8++) acc[r8] = 0.f;
    #pragma unroll 4
    for (int jj = 0; jj < 128; jj++) {
        float vv = vs[jj * 128 + d];
        #pragma unroll
        for (int r8 = 0; r8 < 8; r8++)
            acc[r8] += ps[(rh * 8 + r8) * 128 + jj] * vv;
    }
    #pragma unroll
    for (int r8 = 0; r8 < 8; r8++) {
        int r = rh * 8 + r8;
        o[(size_t)(16*b + r) * D_MOD + h * DHEAD + d] = __float2half_rn(acc[r8] * invr[r8]);
    }
}

// ================ Wo GEMM (M=256) BK=128 + tail residual copy, one launch =======
// Stage layout: A0 4KB | A1 4KB | B0 16KB | B1 16KB = 40KB. 2 stages. 16 iters.
#define STG32B 40960
#define G32_SMEM (2 * STG32B)
#define NS32 16

__global__ __launch_bounds__(256)
void gemm32copy(const __half* __restrict__ A, const __half* __restrict__ B,
                float* __restrict__ C, const float* __restrict__ R,
                const float* __restrict__ x) {
    int bid = blockIdx.x;
    int tid = threadIdx.x;

    if (bid >= 128) {
        const size_t count = (size_t)(N_TOK - NQ) * D_MOD / 4;
        const float4* xs = (const float4*)(x + (size_t)NQ * D_MOD);
        float4* od = (float4*)(C + (size_t)NQ * D_MOD);
        for (size_t i = (size_t)(bid - 128) * 256 + tid; i < count; i += 128 * 256)
            od[i] = xs[i];
        return;
    }

    extern __shared__ __align__(1024) char smem[];
    uint32_t sb = smem_u32(smem);
    int wid = tid >> 5, lane = tid & 31;
    int rowBase = (bid >> 4) * 32, colBase = (bid & 15) * 128;

    float acc[2][2][4];
    #pragma unroll
    for (int mi = 0; mi < 2; mi++)
        #pragma unroll
        for (int ni = 0; ni < 2; ni++)
            #pragma unroll
            for (int r = 0; r < 4; r++) acc[mi][ni][r] = 0.f;

    // stage s covers k in [s*128, (s+1)*128); halves of 64 k each
    auto load_stage = [&](int s) {
        uint32_t so = sb + (uint32_t)(s & 1) * STG32B;
        size_t kof = (size_t)s * 128;
        // A: 32 rows x 16 chunks (16B) = 512
        #pragma unroll
        for (int p = 0; p < 2; p++) {
            int idx = tid + p * 256;
            int row = idx >> 4, c = idx & 15;
            int half = c >> 3, cl = c & 7;
            uint32_t sw = swz((uint32_t)(row * 128 + cl * 16));
            cpa16(so + half * 4096 + sw, A + (size_t)(rowBase + row) * 2048 + kof + c * 8);
        }
        // B: 128 rows x 16 chunks = 2048
        #pragma unroll
        for (int p = 0; p < 8; p++) {
            int idx = tid + p * 256;
            int row = idx >> 4, c = idx & 15;
            int half = c >> 3, cl = c & 7;
            uint32_t sw = swz((uint32_t)(row * 128 + cl * 16));
            cpa16(so + 8192 + half * 16384 + sw,
                  B + (size_t)(colBase + row) * 2048 + kof + c * 8);
        }
        asm volatile("cp.async.commit_group;" ::: "memory");
    };

    load_stage(0);
    load_stage(1);

    for (int s = 0; s < NS32; s++) {
        if (s + 2 < NS32) asm volatile("cp.async.wait_group 1;" ::: "memory");
        else              asm volatile("cp.async.wait_group 0;" ::: "memory");
        __syncthreads();
        uint32_t so = sb + (uint32_t)(s & 1) * STG32B;
        #pragma unroll
        for (int ks = 0; ks < 8; ks++) {
            int sub = ks >> 2, ksl = ks & 3;
            uint32_t aBase = so + (uint32_t)sub * 4096;
            uint32_t bBase = so + 8192 + (uint32_t)sub * 16384;
            uint32_t ah[2][4], bh[4];
            #pragma unroll
            for (int mi = 0; mi < 2; mi++) {
                int row = mi * 16 + (lane & 15);
                int ch  = ksl * 2 + (lane >> 4);
                ldsm4(aBase + swz((uint32_t)(row * 128 + ch * 16)), ah[mi]);
            }
            {
                int row = wid * 16 + ((lane >> 4) << 3) + (lane & 7);
                int ch  = ksl * 2 + ((lane >> 3) & 1);
                ldsm4(bBase + swz((uint32_t)(row * 128 + ch * 16)), bh);
            }
            #pragma unroll
            for (int mi = 0; mi < 2; mi++)
                #pragma unroll
                for (int ni = 0; ni < 2; ni++)
                    mma16816(acc[mi][ni], ah[mi], &bh[ni * 2]);
        }
        __syncthreads();
        if (s + 2 < NS32) load_stage(s + 2);
    }

    #pragma unroll
    for (int mi = 0; mi < 2; mi++)
        #pragma unroll
        for (int ni = 0; ni < 2; ni++) {
            int m0  = rowBase + mi * 16 + (lane >> 2);
            int col = colBase + wid * 16 + ni * 8 + (lane & 3) * 2;
            size_t i0 = (size_t)m0 * 2048 + col;
            size_t i1 = i0 + (size_t)8 * 2048;
            float2 r0 = *(const float2*)(R + i0);
            float2 r1 = *(const float2*)(R + i1);
            *(float2*)(C + i0) = make_float2(acc[mi][ni][0] + r0.x, acc[mi][ni][1] + r0.y);
            *(float2*)(C + i1) = make_float2(acc[mi][ni][2] + r1.x, acc[mi][ni][3] + r1.y);
        }
}

extern "C" void kernel_launch(void* const* d_in, const int* in_sizes, int n_in,
                              void* d_out, int out_size) {
    const float* x  = (const float*)d_in[0];
    const float* Wq = (const float*)d_in[1];
    const float* Wk = (const float*)d_in[2];
    const float* Wv = (const float*)d_in[3];
    const float* Wo = (const float*)d_in[4];
    float* out = (float*)d_out;

    __half *xnh, *wqT, *wkT, *wvT, *woT, *oh, *vh;
    __nv_bfloat16 *kbf, *qbf;
    cudaGetSymbolAddress((void**)&xnh,  g_xnh);
    cudaGetSymbolAddress((void**)&wqT,  g_wqT);
    cudaGetSymbolAddress((void**)&wkT,  g_wkT);
    cudaGetSymbolAddress((void**)&wvT,  g_wvT);
    cudaGetSymbolAddress((void**)&woT,  g_woT);
    cudaGetSymbolAddress((void**)&vh,   g_vh);
    cudaGetSymbolAddress((void**)&kbf,  g_kbf);
    cudaGetSymbolAddress((void**)&qbf,  g_qbf);
    cudaGetSymbolAddress((void**)&oh,   g_oh);

    cudaFuncSetAttribute(proj_gemm,  cudaFuncAttributeMaxDynamicSharedMemorySize, G128_SMEM);
    cudaFuncSetAttribute(gemm32copy, cudaFuncAttributeMaxDynamicSharedMemorySize, G32_SMEM);
    cudaFuncSetAttribute(attn3,      cudaFuncAttributeMaxDynamicSharedMemorySize, ATT3_SMEM);

    // 1) LN -> fp16  +  all weight transposes (one launch, 64x64 tiles)
    prep<<<2048 + 4 * 1024, 256>>>(x, xnh, Wq, Wk, Wv, Wo, wqT, wkT, wvT, woT);
    // 2) Q + K + V projections fused (Q first; K/Q with fused head-LN -> bf16; V fp16)
    proj_gemm<<<544, 256, G128_SMEM>>>(xnh, wkT, wvT, wqT, kbf, vh, qbf);
    // 3) sparse attention -> fp16
    attn3<<<dim3(16, 16), 256, ATT3_SMEM>>>(qbf, kbf, vh, oh);
    // 4) out[0:256] = o @ Wo + x ; out[256:] = x  (one launch, BK=128)
    gemm32copy<<<256, 256, G32_SMEM>>>(oh, woT, out, x, x);
}